// round 5
// baseline (speedup 1.0000x reference)
#include <cuda_runtime.h>
#include <cuda_fp16.h>
#include <cstdint>

// TitansMemoryModule — warp-specialized producer/consumer with mbarrier ring.
//   retrieved = k @ W^T ; G1 = k^T k ; G2 = v^T k
//   grad = (2/numel)(W G1 - G2) ; loss = (<W G1,W> - 2<G2,W> + sum v^2)/numel
// 512 thr/CTA, grid=148 (1 CTA/SM): warps 0-3 producers, 4-11 GEMM1, 12-15 reductions.

#define D     64
#define TILE  128
#define PH    72                     // smem pitch (halves): 144B rows, 16B-aligned, conflict-free
#define DEPTH 4

static constexpr int KBUF  = TILE * PH;           // 9216 halves per tile buffer
static constexpr int STAGE = 2 * KBUF;            // k + v per stage
static constexpr int SMEM_HALVES = DEPTH * STAGE + D * PH;
static constexpr int SMEM_BYTES  = SMEM_HALVES * 2;   // 156672 B

__device__ float g_G1[D * D];
__device__ float g_G2[D * D];
__device__ float g_ksum[D];
__device__ float g_sv;

__device__ __forceinline__ uint32_t sh_u32(const void* p) {
    return (uint32_t)__cvta_generic_to_shared(p);
}
__device__ __forceinline__ void ldsm4(uint32_t& r0, uint32_t& r1, uint32_t& r2, uint32_t& r3, uint32_t a) {
    asm volatile("ldmatrix.sync.aligned.m8n8.x4.shared.b16 {%0,%1,%2,%3},[%4];"
                 : "=r"(r0), "=r"(r1), "=r"(r2), "=r"(r3) : "r"(a));
}
__device__ __forceinline__ void ldsm4t(uint32_t& r0, uint32_t& r1, uint32_t& r2, uint32_t& r3, uint32_t a) {
    asm volatile("ldmatrix.sync.aligned.m8n8.x4.trans.shared.b16 {%0,%1,%2,%3},[%4];"
                 : "=r"(r0), "=r"(r1), "=r"(r2), "=r"(r3) : "r"(a));
}
__device__ __forceinline__ void mma16(float* c,
                                      uint32_t a0, uint32_t a1, uint32_t a2, uint32_t a3,
                                      uint32_t b0, uint32_t b1) {
    asm volatile("mma.sync.aligned.m16n8k16.row.col.f32.f16.f16.f32 "
                 "{%0,%1,%2,%3},{%4,%5,%6,%7},{%8,%9},{%0,%1,%2,%3};"
                 : "+f"(c[0]), "+f"(c[1]), "+f"(c[2]), "+f"(c[3])
                 : "r"(a0), "r"(a1), "r"(a2), "r"(a3), "r"(b0), "r"(b1));
}
__device__ __forceinline__ void mbar_init(uint32_t a, uint32_t cnt) {
    asm volatile("mbarrier.init.shared.b64 [%0], %1;" :: "r"(a), "r"(cnt) : "memory");
}
__device__ __forceinline__ void mbar_arrive(uint32_t a) {
    asm volatile("mbarrier.arrive.shared.b64 _, [%0];" :: "r"(a) : "memory");
}
__device__ __forceinline__ void mbar_wait(uint32_t a, uint32_t parity) {
    asm volatile(
        "{\n\t.reg .pred P;\n"
        "WL_%=:\n\t"
        "mbarrier.try_wait.parity.acquire.cta.shared::cta.b64 P, [%0], %1, 0x989680;\n\t"
        "@P bra WD_%=;\n\t"
        "bra WL_%=;\n"
        "WD_%=:\n\t}"
        :: "r"(a), "r"(parity) : "memory");
}

__global__ void zero_scratch_kernel() {
    int t = blockIdx.x * blockDim.x + threadIdx.x;
    if (t < D * D) { g_G1[t] = 0.0f; g_G2[t] = 0.0f; }
    if (t < D)     g_ksum[t] = 0.0f;
    if (t == 0)    g_sv = 0.0f;
}

__global__ __launch_bounds__(512, 1)
void titans_main_kernel(const float* __restrict__ kmat,
                        const float* __restrict__ vmat,
                        const float* __restrict__ W,
                        float* __restrict__ ret,
                        int N) {
    extern __shared__ __half sh[];
    __shared__ uint64_t mbar[2 * DEPTH];   // [0..3] full, [4..7] empty
    __half* wsh = sh + DEPTH * STAGE;

    const int tid  = threadIdx.x;
    const int lane = tid & 31;
    const int warp = tid >> 5;

    if (tid == 0) {
#pragma unroll
        for (int s = 0; s < DEPTH; s++) {
            mbar_init(sh_u32(&mbar[s]), 128);          // full: 128 producer threads
            mbar_init(sh_u32(&mbar[DEPTH + s]), 12);   // empty: 12 consumer warps
        }
    }
    // stage W (fp16) once
    for (int i = tid; i < D * D; i += 512)
        wsh[(i >> 6) * PH + (i & 63)] = __float2half(W[i]);
    __syncthreads();

    const int grid   = gridDim.x;
    const int ntiles = N / TILE;

    if (warp < 4) {
        // ================= PRODUCERS (128 threads) =================
        const int pt   = tid;                 // 0..127
        const int qcol = (pt & 15) * 4;
        const int rbase = pt >> 4;            // 0..7
        float ks4[4] = {0.f, 0.f, 0.f, 0.f};
        float sv = 0.0f;

        int stage = 0, phase = 1;
        for (int tile = blockIdx.x; tile < ntiles; tile += grid) {
            mbar_wait(sh_u32(&mbar[DEPTH + stage]), phase);
            __half* kb = sh + stage * STAGE;
            __half* vb = kb + KBUF;

            const float4* kt = reinterpret_cast<const float4*>(kmat) + (size_t)tile * 2048;
            const float4* vt = reinterpret_cast<const float4*>(vmat) + (size_t)tile * 2048;

            float4 a[8], b[8];
#pragma unroll
            for (int j = 0; j < 8; j++) a[j] = __ldcs(&kt[pt + j * 128]);
#pragma unroll
            for (int j = 0; j < 8; j++) b[j] = __ldcs(&kt[pt + (j + 8) * 128]);
#pragma unroll
            for (int j = 0; j < 8; j++) {
                float4 x = a[j];
                int r = rbase + j * 8;
                ks4[0] += x.x; ks4[1] += x.y; ks4[2] += x.z; ks4[3] += x.w;
                __half2 h01 = __floats2half2_rn(x.x, x.y);
                __half2 h23 = __floats2half2_rn(x.z, x.w);
                *reinterpret_cast<uint2*>(&kb[r * PH + qcol]) =
                    make_uint2(*reinterpret_cast<uint32_t*>(&h01), *reinterpret_cast<uint32_t*>(&h23));
            }
#pragma unroll
            for (int j = 0; j < 8; j++) {
                float4 x = b[j];
                int r = rbase + (j + 8) * 8;
                ks4[0] += x.x; ks4[1] += x.y; ks4[2] += x.z; ks4[3] += x.w;
                __half2 h01 = __floats2half2_rn(x.x, x.y);
                __half2 h23 = __floats2half2_rn(x.z, x.w);
                *reinterpret_cast<uint2*>(&kb[r * PH + qcol]) =
                    make_uint2(*reinterpret_cast<uint32_t*>(&h01), *reinterpret_cast<uint32_t*>(&h23));
            }
#pragma unroll
            for (int j = 0; j < 8; j++) a[j] = __ldcs(&vt[pt + j * 128]);
#pragma unroll
            for (int j = 0; j < 8; j++) b[j] = __ldcs(&vt[pt + (j + 8) * 128]);
#pragma unroll
            for (int j = 0; j < 8; j++) {
                float4 x = a[j];
                int r = rbase + j * 8;
                sv += x.x * x.x + x.y * x.y + x.z * x.z + x.w * x.w;
                __half2 h01 = __floats2half2_rn(x.x, x.y);
                __half2 h23 = __floats2half2_rn(x.z, x.w);
                *reinterpret_cast<uint2*>(&vb[r * PH + qcol]) =
                    make_uint2(*reinterpret_cast<uint32_t*>(&h01), *reinterpret_cast<uint32_t*>(&h23));
            }
#pragma unroll
            for (int j = 0; j < 8; j++) {
                float4 x = b[j];
                int r = rbase + (j + 8) * 8;
                sv += x.x * x.x + x.y * x.y + x.z * x.z + x.w * x.w;
                __half2 h01 = __floats2half2_rn(x.x, x.y);
                __half2 h23 = __floats2half2_rn(x.z, x.w);
                *reinterpret_cast<uint2*>(&vb[r * PH + qcol]) =
                    make_uint2(*reinterpret_cast<uint32_t*>(&h01), *reinterpret_cast<uint32_t*>(&h23));
            }
            mbar_arrive(sh_u32(&mbar[stage]));
            stage++; if (stage == DEPTH) { stage = 0; phase ^= 1; }
        }
        // epilogue: column sums + sum(v^2)
#pragma unroll
        for (int c = 0; c < 4; c++) atomicAdd(&g_ksum[qcol + c], ks4[c]);
#pragma unroll
        for (int off = 16; off > 0; off >>= 1)
            sv += __shfl_xor_sync(0xFFFFFFFF, sv, off);
        if (lane == 0) atomicAdd(&g_sv, sv);

    } else if (warp < 12) {
        // ================= GEMM1 warps (8): retrieved = k @ W^T =================
        const int widx = warp - 4;
        const int row0 = widx * 16;
        const int lp = lane >> 2, lq = lane & 3;

        // hoist W fragments (constant across tiles)
        uint32_t wr[4][4][4];
#pragma unroll
        for (int kk = 0; kk < 4; kk++)
#pragma unroll
            for (int j = 0; j < 4; j++) {
                const int bt = (2 * j + (lane >> 4)) * 8 + (lane & 7);
                const int bc = kk * 16 + ((lane >> 3) & 1) * 8;
                ldsm4(wr[kk][j][0], wr[kk][j][1], wr[kk][j][2], wr[kk][j][3],
                      sh_u32(&wsh[bt * PH + bc]));
            }

        int stage = 0, phase = 0;
        for (int tile = blockIdx.x; tile < ntiles; tile += grid) {
            mbar_wait(sh_u32(&mbar[stage]), phase);
            const __half* kb = sh + stage * STAGE;

            uint32_t af[4][4];
#pragma unroll
            for (int kk = 0; kk < 4; kk++)
                ldsm4(af[kk][0], af[kk][1], af[kk][2], af[kk][3],
                      sh_u32(&kb[(row0 + (lane & 15)) * PH + kk * 16 + ((lane >> 4) << 3)]));
            if (lane == 0) mbar_arrive(sh_u32(&mbar[DEPTH + stage]));   // done with smem

            float c1[8][4];
#pragma unroll
            for (int n = 0; n < 8; n++)
#pragma unroll
                for (int i = 0; i < 4; i++) c1[n][i] = 0.0f;
#pragma unroll
            for (int kk = 0; kk < 4; kk++)
#pragma unroll
                for (int j = 0; j < 4; j++) {
                    mma16(c1[2 * j],     af[kk][0], af[kk][1], af[kk][2], af[kk][3],
                          wr[kk][j][0], wr[kk][j][1]);
                    mma16(c1[2 * j + 1], af[kk][0], af[kk][1], af[kk][2], af[kk][3],
                          wr[kk][j][2], wr[kk][j][3]);
                }

            const size_t gr0 = (size_t)(tile * TILE + row0 + lp) * D;
#pragma unroll
            for (int n = 0; n < 8; n++) {
                const int col = n * 8 + 2 * lq;
                *reinterpret_cast<float2*>(&ret[gr0 + col])         = make_float2(c1[n][0], c1[n][1]);
                *reinterpret_cast<float2*>(&ret[gr0 + 8 * D + col]) = make_float2(c1[n][2], c1[n][3]);
            }
            stage++; if (stage == DEPTH) { stage = 0; phase ^= 1; }
        }

    } else {
        // ================= Reduction warps (4): G1 = k^T k, G2 = v^T k =================
        const int ridx = warp - 12;
        const int jstripe = (ridx & 1) * 32;
        const bool useV = (ridx >> 1) != 0;           // 0,1 -> G1 ; 2,3 -> G2
        const int lp = lane >> 2, lq = lane & 3;

        float gacc[2][8][4];
#pragma unroll
        for (int mi = 0; mi < 2; mi++)
#pragma unroll
            for (int n = 0; n < 8; n++)
#pragma unroll
                for (int i = 0; i < 4; i++) gacc[mi][n][i] = 0.0f;

        int stage = 0, phase = 0;
        for (int tile = blockIdx.x; tile < ntiles; tile += grid) {
            mbar_wait(sh_u32(&mbar[stage]), phase);
            const __half* kb = sh + stage * STAGE;
            const __half* asrc = useV ? (kb + KBUF) : kb;

#pragma unroll
            for (int kk = 0; kk < 8; kk++) {
                const int sb = kk * 16;
                uint32_t am[2][4];
#pragma unroll
                for (int mi = 0; mi < 2; mi++) {
                    const int jcol = jstripe + mi * 16;
                    ldsm4t(am[mi][0], am[mi][1], am[mi][2], am[mi][3],
                           sh_u32(&asrc[(sb + ((lane >> 4) << 3) + (lane & 7)) * PH
                                        + jcol + ((lane >> 3) & 1) * 8]));
                }
                const int srow = sb + ((lane >> 3) & 1) * 8 + (lane & 7);
#pragma unroll
                for (int jn = 0; jn < 4; jn++) {
                    const int dcol = (2 * jn + (lane >> 4)) * 8;
                    uint32_t b0, b1, b2, b3;
                    ldsm4t(b0, b1, b2, b3, sh_u32(&kb[srow * PH + dcol]));
#pragma unroll
                    for (int mi = 0; mi < 2; mi++) {
                        mma16(gacc[mi][2 * jn],     am[mi][0], am[mi][1], am[mi][2], am[mi][3], b0, b1);
                        mma16(gacc[mi][2 * jn + 1], am[mi][0], am[mi][1], am[mi][2], am[mi][3], b2, b3);
                    }
                }
            }
            if (lane == 0) mbar_arrive(sh_u32(&mbar[DEPTH + stage]));
            stage++; if (stage == DEPTH) { stage = 0; phase ^= 1; }
        }

        float* gdst = useV ? g_G2 : g_G1;
#pragma unroll
        for (int mi = 0; mi < 2; mi++)
#pragma unroll
            for (int n = 0; n < 8; n++) {
                const int col = n * 8 + 2 * lq;
                const int r0i = (jstripe + mi * 16 + lp) * D;
                const int r1i = (jstripe + mi * 16 + lp + 8) * D;
                atomicAdd(&gdst[r0i + col],     gacc[mi][n][0]);
                atomicAdd(&gdst[r0i + col + 1], gacc[mi][n][1]);
                atomicAdd(&gdst[r1i + col],     gacc[mi][n][2]);
                atomicAdd(&gdst[r1i + col + 1], gacc[mi][n][3]);
            }
    }
}

__global__ void titans_final_kernel(const float* __restrict__ W,
                                    const float* __restrict__ gate_w,
                                    const float* __restrict__ gate_b,
                                    const float* __restrict__ S,
                                    float* __restrict__ out,
                                    int N) {
    __shared__ float Wsh[D * D];
    __shared__ float G1sh[D * D];
    __shared__ float gates_sh[3];
    __shared__ float red[256];
    __shared__ float red2[256];
    __shared__ float scale_sh;
    const int tid = threadIdx.x;
    const float numel = (float)N * (float)D;

    const size_t loss_off = (size_t)N * D;
    const size_t nw_off   = loss_off + 1;
    const size_t ns_off   = nw_off + D * D;
    const size_t g_off    = ns_off + D * D;

    for (int i = tid; i < D * D; i += 256) {
        Wsh[i]  = W[i];
        G1sh[i] = g_G1[i];
    }
    if (tid == 0) {
        float invN = 1.0f / (float)N;
        for (int i = 0; i < 3; i++) {
            float s = gate_b[i];
            for (int d = 0; d < D; d++) s += gate_w[i * D + d] * (g_ksum[d] * invN);
            gates_sh[i] = 1.0f / (1.0f + __expf(-s));
        }
    }
    __syncthreads();
    const float alpha = gates_sh[0];
    const float eta   = gates_sh[1];
    const float theta = gates_sh[2];

    float wg1[16];
    float dWW = 0.0f, dG2W = 0.0f;
#pragma unroll
    for (int i = 0; i < 16; i++) {
        int idx = tid * 16 + i;
        int j = idx >> 6, dp = idx & 63;
        float acc = 0.0f;
#pragma unroll 8
        for (int d = 0; d < D; d++)
            acc += Wsh[j * D + d] * G1sh[d * D + dp];
        wg1[i] = acc;
        dWW  += acc * Wsh[idx];
        dG2W += g_G2[idx] * Wsh[idx];
    }

    float wlocal[16];
    float ss = 0.0f;
#pragma unroll
    for (int i = 0; i < 16; i++) {
        int idx = tid * 16 + i;
        float g = (wg1[i] - g_G2[idx]) * (2.0f / numel);
        g = fminf(1.0f, fmaxf(-1.0f, g));
        float ns = eta * S[idx] - 0.01f * theta * g;
        float nw = (1.0f - alpha) * Wsh[idx] + ns;
        out[ns_off + idx] = ns;
        wlocal[i] = nw;
        ss += nw * nw;
    }

    red[tid]  = ss;
    red2[tid] = dWW - 2.0f * dG2W;
    __syncthreads();
#pragma unroll
    for (int s = 128; s > 0; s >>= 1) {
        if (tid < s) { red[tid] += red[tid + s]; red2[tid] += red2[tid + s]; }
        __syncthreads();
    }
    if (tid == 0) {
        float wnorm = sqrtf(red[0]);
        scale_sh = (wnorm > 10.0f) ? (10.0f / (wnorm + 1e-8f)) : 1.0f;
        out[loss_off] = (g_sv + red2[0]) / numel;
    }
    __syncthreads();
    const float sc = scale_sh;
#pragma unroll
    for (int i = 0; i < 16; i++) {
        int idx = tid * 16 + i;
        out[nw_off + idx] = wlocal[i] * sc;
    }
    if (tid < 3) out[g_off + tid] = gates_sh[tid];
}

extern "C" void kernel_launch(void* const* d_in, const int* in_sizes, int n_in,
                              void* d_out, int out_size) {
    const float* k  = (const float*)d_in[0];
    const float* v  = (const float*)d_in[1];
    const float* W  = (const float*)d_in[2];
    const float* gw = (const float*)d_in[3];
    const float* gb = (const float*)d_in[4];
    const float* S  = (const float*)d_in[5];
    float* out = (float*)d_out;

    const int N = in_sizes[0] / D;

    cudaFuncSetAttribute(titans_main_kernel,
                         cudaFuncAttributeMaxDynamicSharedMemorySize, SMEM_BYTES);

    zero_scratch_kernel<<<16, 256>>>();
    titans_main_kernel<<<148, 512, SMEM_BYTES>>>(k, v, W, out, N);
    titans_final_kernel<<<1, 256>>>(W, gw, gb, S, out, N);
}

// round 7
// speedup vs baseline: 1.0092x; 1.0092x over previous
#include <cuda_runtime.h>
#include <cuda_fp16.h>
#include <cstdint>

// TitansMemoryModule — warp-specialized mbarrier ring + symmetric-G1 tensor reduction.
//   retrieved = k @ W^T ; G1 = k^T k (upper blocks only; symmetric) ; G2 = v^T k
//   grad = (2/numel)(W G1 - G2) ; loss = (<W G1,W> - 2<G2,W> + sum v^2)/numel
// 512 thr/CTA, grid=148: warps 0-3 producers, 4-11 GEMM1, 12-15 reductions (balanced 104 mma each).

#define D     64
#define TILE  128
#define PH    72                     // smem pitch (halves): 144B rows, conflict-free
#define DEPTH 4

static constexpr int KBUF  = TILE * PH;
static constexpr int STAGE = 2 * KBUF;
static constexpr int SMEM_HALVES = DEPTH * STAGE + D * PH;
static constexpr int SMEM_BYTES  = SMEM_HALVES * 2;   // 156672 B

__device__ float g_G1[D * D];     // zero-init at load; re-zeroed by final kernel
__device__ float g_G2[D * D];
__device__ float g_ksum[D];
__device__ float g_sv;

__device__ __forceinline__ uint32_t sh_u32(const void* p) {
    return (uint32_t)__cvta_generic_to_shared(p);
}
__device__ __forceinline__ void ldsm4(uint32_t& r0, uint32_t& r1, uint32_t& r2, uint32_t& r3, uint32_t a) {
    asm volatile("ldmatrix.sync.aligned.m8n8.x4.shared.b16 {%0,%1,%2,%3},[%4];"
                 : "=r"(r0), "=r"(r1), "=r"(r2), "=r"(r3) : "r"(a));
}
__device__ __forceinline__ void ldsm4t(uint32_t& r0, uint32_t& r1, uint32_t& r2, uint32_t& r3, uint32_t a) {
    asm volatile("ldmatrix.sync.aligned.m8n8.x4.trans.shared.b16 {%0,%1,%2,%3},[%4];"
                 : "=r"(r0), "=r"(r1), "=r"(r2), "=r"(r3) : "r"(a));
}
__device__ __forceinline__ void mma16(float* c,
                                      uint32_t a0, uint32_t a1, uint32_t a2, uint32_t a3,
                                      uint32_t b0, uint32_t b1) {
    asm volatile("mma.sync.aligned.m16n8k16.row.col.f32.f16.f16.f32 "
                 "{%0,%1,%2,%3},{%4,%5,%6,%7},{%8,%9},{%0,%1,%2,%3};"
                 : "+f"(c[0]), "+f"(c[1]), "+f"(c[2]), "+f"(c[3])
                 : "r"(a0), "r"(a1), "r"(a2), "r"(a3), "r"(b0), "r"(b1));
}
__device__ __forceinline__ void mbar_init(uint32_t a, uint32_t cnt) {
    asm volatile("mbarrier.init.shared.b64 [%0], %1;" :: "r"(a), "r"(cnt) : "memory");
}
__device__ __forceinline__ void mbar_arrive(uint32_t a) {
    asm volatile("mbarrier.arrive.shared.b64 _, [%0];" :: "r"(a) : "memory");
}
__device__ __forceinline__ void mbar_wait(uint32_t a, uint32_t parity) {
    asm volatile(
        "{\n\t.reg .pred P;\n"
        "WL_%=:\n\t"
        "mbarrier.try_wait.parity.acquire.cta.shared::cta.b64 P, [%0], %1, 0x989680;\n\t"
        "@P bra WD_%=;\n\t"
        "bra WL_%=;\n"
        "WD_%=:\n\t}"
        :: "r"(a), "r"(parity) : "memory");
}

// ---- reduction work tables: enc = src<<6 | arow<<4 | acol<<2 | khalf_mask ----
#define EK(ar,ac,m) ((0<<6)|((ar)<<4)|((ac)<<2)|(m))
#define EV(ar,ac,m) ((1<<6)|((ar)<<4)|((ac)<<2)|(m))
#define W0L EK(0,0,3),EK(0,1,3),EK(0,2,3),EK(0,3,3),EK(1,1,3),EK(1,2,3),EK(1,3,1)
#define W1L EK(1,3,2),EK(2,2,3),EK(2,3,3),EK(3,3,3),EV(0,0,3),EV(0,1,3),EV(0,2,3)
#define W2L EV(0,3,3),EV(1,0,3),EV(1,1,3),EV(1,2,3),EV(1,3,3),EV(2,0,3),EV(2,1,1)
#define W3L EV(2,1,2),EV(2,2,3),EV(2,3,3),EV(3,0,3),EV(3,1,3),EV(3,2,3),EV(3,3,3)
static __device__ const int RTBL[4][7] = {{W0L},{W1L},{W2L},{W3L}};

template<int E>
__device__ __forceinline__ void red_block(float* acc, const __half* kb, const __half* vb, int lane) {
    constexpr int src = (E >> 6) & 1, ar = (E >> 4) & 3, ac = (E >> 2) & 3, khm = E & 3;
    const __half* ab = src ? vb : kb;
    const int jcol     = ar * 16 + ((lane >> 3) & 1) * 8;
    const int arow_sel = ((lane >> 4) << 3) + (lane & 7);
    const int bcol     = ac * 16 + (lane >> 4) * 8;
    const int brow_sel = ((lane >> 3) & 1) * 8 + (lane & 7);
#pragma unroll
    for (int kk = 0; kk < 8; kk++) {
        if (((khm >> (kk >> 2)) & 1) == 0) continue;   // khm constexpr -> folded
        const int sb = kk * 16;
        uint32_t a0, a1, a2, a3, b0, b1, b2, b3;
        ldsm4t(a0, a1, a2, a3, sh_u32(&ab[(sb + arow_sel) * PH + jcol]));
        ldsm4t(b0, b1, b2, b3, sh_u32(&kb[(sb + brow_sel) * PH + bcol]));
        mma16(acc,     a0, a1, a2, a3, b0, b1);
        mma16(acc + 4, a0, a1, a2, a3, b2, b3);
    }
}

template<int E0,int E1,int E2,int E3,int E4,int E5,int E6>
__device__ __forceinline__ void red_run(float (&acc)[7][8], const __half* kb, const __half* vb, int lane) {
    red_block<E0>(acc[0], kb, vb, lane); red_block<E1>(acc[1], kb, vb, lane);
    red_block<E2>(acc[2], kb, vb, lane); red_block<E3>(acc[3], kb, vb, lane);
    red_block<E4>(acc[4], kb, vb, lane); red_block<E5>(acc[5], kb, vb, lane);
    red_block<E6>(acc[6], kb, vb, lane);
}

__global__ void noop_kernel() {}

__global__ __launch_bounds__(512, 1)
void titans_main_kernel(const float* __restrict__ kmat,
                        const float* __restrict__ vmat,
                        const float* __restrict__ W,
                        float* __restrict__ ret,
                        int N) {
    extern __shared__ __half sh[];
    __shared__ uint64_t mbar[2 * DEPTH];   // [0..3] full, [4..7] empty
    __half* wsh = sh + DEPTH * STAGE;

    const int tid  = threadIdx.x;
    const int lane = tid & 31;
    const int warp = tid >> 5;

    if (tid == 0) {
#pragma unroll
        for (int s = 0; s < DEPTH; s++) {
            mbar_init(sh_u32(&mbar[s]), 128);          // full: 128 producer threads
            mbar_init(sh_u32(&mbar[DEPTH + s]), 12);   // empty: 12 consumer warps
        }
    }
    for (int i = tid; i < D * D; i += 512)
        wsh[(i >> 6) * PH + (i & 63)] = __float2half(W[i]);
    __syncthreads();

    const int grid   = gridDim.x;
    const int ntiles = N / TILE;

    if (warp < 4) {
        // ================= PRODUCERS (128 threads) =================
        const int pt    = tid;
        const int qcol  = (pt & 15) * 4;
        const int rbase = pt >> 4;
        float ks4[4] = {0.f, 0.f, 0.f, 0.f};
        float sv = 0.0f;

        int stage = 0, phase = 1;
        for (int tile = blockIdx.x; tile < ntiles; tile += grid) {
            mbar_wait(sh_u32(&mbar[DEPTH + stage]), phase);
            __half* kb = sh + stage * STAGE;
            __half* vb = kb + KBUF;
            const float4* kt = reinterpret_cast<const float4*>(kmat) + (size_t)tile * 2048;
            const float4* vt = reinterpret_cast<const float4*>(vmat) + (size_t)tile * 2048;

            float4 a[8], b[8];
#pragma unroll
            for (int j = 0; j < 8; j++) a[j] = __ldcs(&kt[pt + j * 128]);
#pragma unroll
            for (int j = 0; j < 8; j++) b[j] = __ldcs(&kt[pt + (j + 8) * 128]);
#pragma unroll
            for (int j = 0; j < 16; j++) {
                float4 x = (j < 8) ? a[j] : b[j - 8];
                int r = rbase + j * 8;
                ks4[0] += x.x; ks4[1] += x.y; ks4[2] += x.z; ks4[3] += x.w;
                __half2 h01 = __floats2half2_rn(x.x, x.y);
                __half2 h23 = __floats2half2_rn(x.z, x.w);
                *reinterpret_cast<uint2*>(&kb[r * PH + qcol]) =
                    make_uint2(*reinterpret_cast<uint32_t*>(&h01), *reinterpret_cast<uint32_t*>(&h23));
            }
#pragma unroll
            for (int j = 0; j < 8; j++) a[j] = __ldcs(&vt[pt + j * 128]);
#pragma unroll
            for (int j = 0; j < 8; j++) b[j] = __ldcs(&vt[pt + (j + 8) * 128]);
#pragma unroll
            for (int j = 0; j < 16; j++) {
                float4 x = (j < 8) ? a[j] : b[j - 8];
                int r = rbase + j * 8;
                sv += x.x * x.x + x.y * x.y + x.z * x.z + x.w * x.w;
                __half2 h01 = __floats2half2_rn(x.x, x.y);
                __half2 h23 = __floats2half2_rn(x.z, x.w);
                *reinterpret_cast<uint2*>(&vb[r * PH + qcol]) =
                    make_uint2(*reinterpret_cast<uint32_t*>(&h01), *reinterpret_cast<uint32_t*>(&h23));
            }
            mbar_arrive(sh_u32(&mbar[stage]));
            stage++; if (stage == DEPTH) { stage = 0; phase ^= 1; }
        }
#pragma unroll
        for (int c = 0; c < 4; c++) atomicAdd(&g_ksum[qcol + c], ks4[c]);
#pragma unroll
        for (int off = 16; off > 0; off >>= 1)
            sv += __shfl_xor_sync(0xFFFFFFFF, sv, off);
        if (lane == 0) atomicAdd(&g_sv, sv);

    } else if (warp < 12) {
        // ================= GEMM1 warps (8): retrieved = k @ W^T =================
        const int widx = warp - 4;
        const int row0 = widx * 16;
        const int lp = lane >> 2, lq = lane & 3;

        uint32_t wr[4][4][4];
#pragma unroll
        for (int kk = 0; kk < 4; kk++)
#pragma unroll
            for (int j = 0; j < 4; j++) {
                const int bt = (2 * j + (lane >> 4)) * 8 + (lane & 7);
                const int bc = kk * 16 + ((lane >> 3) & 1) * 8;
                ldsm4(wr[kk][j][0], wr[kk][j][1], wr[kk][j][2], wr[kk][j][3],
                      sh_u32(&wsh[bt * PH + bc]));
            }

        int stage = 0, phase = 0;
        for (int tile = blockIdx.x; tile < ntiles; tile += grid) {
            mbar_wait(sh_u32(&mbar[stage]), phase);
            const __half* kb = sh + stage * STAGE;

            uint32_t af[4][4];
#pragma unroll
            for (int kk = 0; kk < 4; kk++)
                ldsm4(af[kk][0], af[kk][1], af[kk][2], af[kk][3],
                      sh_u32(&kb[(row0 + (lane & 15)) * PH + kk * 16 + ((lane >> 4) << 3)]));
            if (lane == 0) mbar_arrive(sh_u32(&mbar[DEPTH + stage]));

            float c1[8][4];
#pragma unroll
            for (int n = 0; n < 8; n++)
#pragma unroll
                for (int i = 0; i < 4; i++) c1[n][i] = 0.0f;
#pragma unroll
            for (int kk = 0; kk < 4; kk++)
#pragma unroll
                for (int j = 0; j < 4; j++) {
                    mma16(c1[2 * j],     af[kk][0], af[kk][1], af[kk][2], af[kk][3],
                          wr[kk][j][0], wr[kk][j][1]);
                    mma16(c1[2 * j + 1], af[kk][0], af[kk][1], af[kk][2], af[kk][3],
                          wr[kk][j][2], wr[kk][j][3]);
                }

            const size_t gr0 = (size_t)(tile * TILE + row0 + lp) * D;
#pragma unroll
            for (int n = 0; n < 8; n++) {
                const int col = n * 8 + 2 * lq;
                *reinterpret_cast<float2*>(&ret[gr0 + col])         = make_float2(c1[n][0], c1[n][1]);
                *reinterpret_cast<float2*>(&ret[gr0 + 8 * D + col]) = make_float2(c1[n][2], c1[n][3]);
            }
            stage++; if (stage == DEPTH) { stage = 0; phase ^= 1; }
        }

    } else {
        // ================= Reduction warps (4): G1 upper-tri + G2, 104 mma each =================
        const int ridx = warp - 12;
        const int lp = lane >> 2, lq = lane & 3;

        float acc[7][8];
#pragma unroll
        for (int b = 0; b < 7; b++)
#pragma unroll
            for (int i = 0; i < 8; i++) acc[b][i] = 0.0f;

        int stage = 0, phase = 0;
        for (int tile = blockIdx.x; tile < ntiles; tile += grid) {
            mbar_wait(sh_u32(&mbar[stage]), phase);
            const __half* kb = sh + stage * STAGE;
            const __half* vb = kb + KBUF;

            switch (ridx) {
                case 0: red_run<W0L>(acc, kb, vb, lane); break;
                case 1: red_run<W1L>(acc, kb, vb, lane); break;
                case 2: red_run<W2L>(acc, kb, vb, lane); break;
                default: red_run<W3L>(acc, kb, vb, lane); break;
            }
            if (lane == 0) mbar_arrive(sh_u32(&mbar[DEPTH + stage]));
            stage++; if (stage == DEPTH) { stage = 0; phase ^= 1; }
        }

#pragma unroll
        for (int b = 0; b < 7; b++) {
            const int enc = RTBL[ridx][b];
            const int src = (enc >> 6) & 1, ar = (enc >> 4) & 3, ac = (enc >> 2) & 3;
            float* gd = src ? g_G2 : g_G1;
            const int r0 = (ar * 16 + lp) * D + ac * 16;
            const int r1 = (ar * 16 + 8 + lp) * D + ac * 16;
            atomicAdd(&gd[r0 + 2 * lq],         acc[b][0]);
            atomicAdd(&gd[r0 + 2 * lq + 1],     acc[b][1]);
            atomicAdd(&gd[r1 + 2 * lq],         acc[b][2]);
            atomicAdd(&gd[r1 + 2 * lq + 1],     acc[b][3]);
            atomicAdd(&gd[r0 + 8 + 2 * lq],     acc[b][4]);
            atomicAdd(&gd[r0 + 8 + 2 * lq + 1], acc[b][5]);
            atomicAdd(&gd[r1 + 8 + 2 * lq],     acc[b][6]);
            atomicAdd(&gd[r1 + 8 + 2 * lq + 1], acc[b][7]);
        }
    }
}

__global__ void titans_final_kernel(const float* __restrict__ W,
                                    const float* __restrict__ gate_w,
                                    const float* __restrict__ gate_b,
                                    const float* __restrict__ S,
                                    float* __restrict__ out,
                                    int N) {
    __shared__ float Wsh[D * D];
    __shared__ float G1sh[D * D];
    __shared__ float gates_sh[3];
    __shared__ float red[256];
    __shared__ float red2[256];
    __shared__ float scale_sh;
    const int tid = threadIdx.x;
    const float numel = (float)N * (float)D;

    const size_t loss_off = (size_t)N * D;
    const size_t nw_off   = loss_off + 1;
    const size_t ns_off   = nw_off + D * D;
    const size_t g_off    = ns_off + D * D;

    for (int i = tid; i < D * D; i += 256) {
        Wsh[i] = W[i];
        const int j = i >> 6, d = i & 63;
        // G1 symmetric: lower blocks mirrored from upper
        G1sh[i] = ((j >> 4) <= (d >> 4)) ? g_G1[i] : g_G1[(d << 6) | j];
    }
    if (tid == 0) {
        float invN = 1.0f / (float)N;
        for (int i = 0; i < 3; i++) {
            float sg = gate_b[i];
            for (int d = 0; d < D; d++) sg += gate_w[i * D + d] * (g_ksum[d] * invN);
            gates_sh[i] = 1.0f / (1.0f + __expf(-sg));
        }
    }
    __syncthreads();
    const float alpha = gates_sh[0];
    const float eta   = gates_sh[1];
    const float theta = gates_sh[2];

    float wg1[16];
    float dWW = 0.0f, dG2W = 0.0f;
#pragma unroll
    for (int i = 0; i < 16; i++) {
        int idx = tid * 16 + i;
        int j = idx >> 6, dp = idx & 63;
        float a = 0.0f;
#pragma unroll 8
        for (int d = 0; d < D; d++)
            a += Wsh[j * D + d] * G1sh[d * D + dp];
        wg1[i] = a;
        dWW  += a * Wsh[idx];
        dG2W += g_G2[idx] * Wsh[idx];
    }

    float wlocal[16];
    float ss = 0.0f;
#pragma unroll
    for (int i = 0; i < 16; i++) {
        int idx = tid * 16 + i;
        float g = (wg1[i] - g_G2[idx]) * (2.0f / numel);
        g = fminf(1.0f, fmaxf(-1.0f, g));
        float ns = eta * S[idx] - 0.01f * theta * g;
        float nw = (1.0f - alpha) * Wsh[idx] + ns;
        out[ns_off + idx] = ns;
        wlocal[i] = nw;
        ss += nw * nw;
    }

    red[tid]  = ss;
    red2[tid] = dWW - 2.0f * dG2W;
    __syncthreads();
#pragma unroll
    for (int s = 128; s > 0; s >>= 1) {
        if (tid < s) { red[tid] += red[tid + s]; red2[tid] += red2[tid + s]; }
        __syncthreads();
    }
    if (tid == 0) {
        float wnorm = sqrtf(red[0]);
        scale_sh = (wnorm > 10.0f) ? (10.0f / (wnorm + 1e-8f)) : 1.0f;
        out[loss_off] = (g_sv + red2[0]) / numel;
    }
    __syncthreads();
    const float sc = scale_sh;
#pragma unroll
    for (int i = 0; i < 16; i++) {
        int idx = tid * 16 + i;
        out[nw_off + idx] = wlocal[i] * sc;
    }
    if (tid < 3) out[g_off + tid] = gates_sh[tid];

    // re-zero scratch for the next graph replay (all reads above are complete)
    __syncthreads();
    for (int i = tid; i < D * D; i += 256) { g_G1[i] = 0.0f; g_G2[i] = 0.0f; }
    if (tid < D) g_ksum[tid] = 0.0f;
    if (tid == 0) g_sv = 0.0f;
}

extern "C" void kernel_launch(void* const* d_in, const int* in_sizes, int n_in,
                              void* d_out, int out_size) {
    const float* k  = (const float*)d_in[0];
    const float* v  = (const float*)d_in[1];
    const float* W  = (const float*)d_in[2];
    const float* gw = (const float*)d_in[3];
    const float* gb = (const float*)d_in[4];
    const float* S  = (const float*)d_in[5];
    float* out = (float*)d_out;

    const int N = in_sizes[0] / D;

    cudaFuncSetAttribute(titans_main_kernel,
                         cudaFuncAttributeMaxDynamicSharedMemorySize, SMEM_BYTES);

    // 4 launches/call so ncu -s 5 lands on titans_main_kernel (launch #5 = main of replay 1)
    noop_kernel<<<1, 32>>>();
    titans_main_kernel<<<148, 512, SMEM_BYTES>>>(k, v, W, out, N);
    titans_final_kernel<<<1, 256>>>(W, gw, gb, S, out, N);
    noop_kernel<<<1, 32>>>();
}

// round 8
// speedup vs baseline: 1.0409x; 1.0315x over previous
#include <cuda_runtime.h>
#include <cuda_fp16.h>
#include <cstdint>

// TitansMemoryModule — pipelined producers (8 warps) + fragment-reuse reductions.
//   retrieved = k @ W^T ; G1 = k^T k (upper blocks, symmetric) ; G2 = v^T k
//   grad = (2/numel)(W G1 - G2) ; loss = (<W G1,W> - 2<G2,W> + sum v^2)/numel
// 512 thr: w0-3 k-producers, w4-7 v-producers, w8-11 GEMM1 (M=32 each), w12-15 reductions.

#define D     64
#define TILE  128
#define PH    72
#define DEPTH 4

static constexpr int KBUF  = TILE * PH;
static constexpr int STAGE = 2 * KBUF;
static constexpr int SMEM_HALVES = DEPTH * STAGE + D * PH;
static constexpr int SMEM_BYTES  = SMEM_HALVES * 2;   // 156672 B

__device__ float g_G1[D * D];     // zero-init at load; re-zeroed by final kernel
__device__ float g_G2[D * D];
__device__ float g_ksum[D];
__device__ float g_sv;

__device__ __forceinline__ uint32_t sh_u32(const void* p) {
    return (uint32_t)__cvta_generic_to_shared(p);
}
__device__ __forceinline__ void ldsm4(uint32_t& r0, uint32_t& r1, uint32_t& r2, uint32_t& r3, uint32_t a) {
    asm volatile("ldmatrix.sync.aligned.m8n8.x4.shared.b16 {%0,%1,%2,%3},[%4];"
                 : "=r"(r0), "=r"(r1), "=r"(r2), "=r"(r3) : "r"(a));
}
__device__ __forceinline__ void ldsm4t(uint32_t& r0, uint32_t& r1, uint32_t& r2, uint32_t& r3, uint32_t a) {
    asm volatile("ldmatrix.sync.aligned.m8n8.x4.trans.shared.b16 {%0,%1,%2,%3},[%4];"
                 : "=r"(r0), "=r"(r1), "=r"(r2), "=r"(r3) : "r"(a));
}
__device__ __forceinline__ void mma16(float* c,
                                      uint32_t a0, uint32_t a1, uint32_t a2, uint32_t a3,
                                      uint32_t b0, uint32_t b1) {
    asm volatile("mma.sync.aligned.m16n8k16.row.col.f32.f16.f16.f32 "
                 "{%0,%1,%2,%3},{%4,%5,%6,%7},{%8,%9},{%0,%1,%2,%3};"
                 : "+f"(c[0]), "+f"(c[1]), "+f"(c[2]), "+f"(c[3])
                 : "r"(a0), "r"(a1), "r"(a2), "r"(a3), "r"(b0), "r"(b1));
}
__device__ __forceinline__ void mbar_init(uint32_t a, uint32_t cnt) {
    asm volatile("mbarrier.init.shared.b64 [%0], %1;" :: "r"(a), "r"(cnt) : "memory");
}
__device__ __forceinline__ void mbar_arrive(uint32_t a) {
    asm volatile("mbarrier.arrive.shared.b64 _, [%0];" :: "r"(a) : "memory");
}
__device__ __forceinline__ void mbar_wait(uint32_t a, uint32_t parity) {
    asm volatile(
        "{\n\t.reg .pred P;\n"
        "WL_%=:\n\t"
        "mbarrier.try_wait.parity.acquire.cta.shared::cta.b64 P, [%0], %1, 0x989680;\n\t"
        "@P bra WD_%=;\n\t"
        "bra WL_%=;\n"
        "WD_%=:\n\t}"
        :: "r"(a), "r"(parity) : "memory");
}

// ---- reduction helpers (fragment layouts identical to R4/R7, numerically verified) ----
__device__ __forceinline__ void ldAfrag(uint32_t* f, const __half* mb, int sb, int ar, int lane) {
    const int asel = ((lane >> 4) << 3) + (lane & 7);
    const int aoff = ((lane >> 3) & 1) * 8;
    ldsm4t(f[0], f[1], f[2], f[3], sh_u32(&mb[(sb + asel) * PH + ar * 16 + aoff]));
}
__device__ __forceinline__ void ldBfrag(uint32_t* f, const __half* kb, int sb, int ac, int lane) {
    const int bsel = ((lane >> 3) & 1) * 8 + (lane & 7);
    const int boff = (lane >> 4) * 8;
    ldsm4t(f[0], f[1], f[2], f[3], sh_u32(&kb[(sb + bsel) * PH + ac * 16 + boff]));
}
__device__ __forceinline__ void bmma(float* acc, const uint32_t* A, const uint32_t* B) {
    mma16(acc,     A[0], A[1], A[2], A[3], B[0], B[1]);
    mma16(acc + 4, A[0], A[1], A[2], A[3], B[2], B[3]);
}

// writeout tables: enc = src<<4 | ar<<2 | ac
static __device__ const int RW_TBL[4][7] = {
    { 0,  1,  2,  3,  5,  6,  7},          // w12: G1 (0,0..3),(1,1..3)
    {10, 11, 15, 16, 17, 18, 19},          // w13: G1 (2,2),(2,3),(3,3) + G2 (0,0..3)
    {20, 21, 22, 23, 24, 25, 25},          // w14: G2 (1,0..3),(2,0),(2,1)   [6 used]
    {26, 27, 28, 29, 30, 31, 31},          // w15: G2 (2,2),(2,3),(3,0..3)   [6 used]
};
static __device__ const int RW_CNT[4] = {7, 7, 6, 6};

__device__ __forceinline__ void red_tile_w0(float (&acc)[7][8], const __half* kb, const __half*, int lane) {
#pragma unroll
    for (int kk = 0; kk < 8; kk++) {
        const int sb = kk * 16;
        uint32_t A0[4], A1[4], B[4][4];
        ldAfrag(A0, kb, sb, 0, lane); ldAfrag(A1, kb, sb, 1, lane);
#pragma unroll
        for (int ac = 0; ac < 4; ac++) ldBfrag(B[ac], kb, sb, ac, lane);
        bmma(acc[0], A0, B[0]); bmma(acc[1], A0, B[1]);
        bmma(acc[2], A0, B[2]); bmma(acc[3], A0, B[3]);
        bmma(acc[4], A1, B[1]); bmma(acc[5], A1, B[2]); bmma(acc[6], A1, B[3]);
    }
}
__device__ __forceinline__ void red_tile_w1(float (&acc)[7][8], const __half* kb, const __half* vb, int lane) {
#pragma unroll
    for (int kk = 0; kk < 8; kk++) {
        const int sb = kk * 16;
        uint32_t A2[4], A3[4], AV[4], B[4][4];
        ldAfrag(A2, kb, sb, 2, lane); ldAfrag(A3, kb, sb, 3, lane); ldAfrag(AV, vb, sb, 0, lane);
#pragma unroll
        for (int ac = 0; ac < 4; ac++) ldBfrag(B[ac], kb, sb, ac, lane);
        bmma(acc[0], A2, B[2]); bmma(acc[1], A2, B[3]); bmma(acc[2], A3, B[3]);
        bmma(acc[3], AV, B[0]); bmma(acc[4], AV, B[1]);
        bmma(acc[5], AV, B[2]); bmma(acc[6], AV, B[3]);
    }
}
__device__ __forceinline__ void red_tile_w2(float (&acc)[7][8], const __half* kb, const __half* vb, int lane) {
#pragma unroll
    for (int kk = 0; kk < 8; kk++) {
        const int sb = kk * 16;
        uint32_t A1[4], A2[4], B[4][4];
        ldAfrag(A1, vb, sb, 1, lane); ldAfrag(A2, vb, sb, 2, lane);
#pragma unroll
        for (int ac = 0; ac < 4; ac++) ldBfrag(B[ac], kb, sb, ac, lane);
        bmma(acc[0], A1, B[0]); bmma(acc[1], A1, B[1]);
        bmma(acc[2], A1, B[2]); bmma(acc[3], A1, B[3]);
        bmma(acc[4], A2, B[0]); bmma(acc[5], A2, B[1]);
    }
}
__device__ __forceinline__ void red_tile_w3(float (&acc)[7][8], const __half* kb, const __half* vb, int lane) {
#pragma unroll
    for (int kk = 0; kk < 8; kk++) {
        const int sb = kk * 16;
        uint32_t A2[4], A3[4], B[4][4];
        ldAfrag(A2, vb, sb, 2, lane); ldAfrag(A3, vb, sb, 3, lane);
#pragma unroll
        for (int ac = 0; ac < 4; ac++) ldBfrag(B[ac], kb, sb, ac, lane);
        bmma(acc[0], A2, B[2]); bmma(acc[1], A2, B[3]);
        bmma(acc[2], A3, B[0]); bmma(acc[3], A3, B[1]);
        bmma(acc[4], A3, B[2]); bmma(acc[5], A3, B[3]);
    }
}

__global__ __launch_bounds__(512, 1)
void titans_main_kernel(const float* __restrict__ kmat,
                        const float* __restrict__ vmat,
                        const float* __restrict__ W,
                        float* __restrict__ ret,
                        int N) {
    extern __shared__ __half sh[];
    __shared__ uint64_t mbar[2 * DEPTH];   // [0..3] full, [4..7] empty
    __half* wsh = sh + DEPTH * STAGE;

    const int tid  = threadIdx.x;
    const int lane = tid & 31;
    const int warp = tid >> 5;

    if (tid == 0) {
#pragma unroll
        for (int s = 0; s < DEPTH; s++) {
            mbar_init(sh_u32(&mbar[s]), 256);          // full: 256 producer threads
            mbar_init(sh_u32(&mbar[DEPTH + s]), 8);    // empty: 8 consumer warps
        }
    }
    for (int i = tid; i < D * D; i += 512)
        wsh[(i >> 6) * PH + (i & 63)] = __float2half(W[i]);
    __syncthreads();

    const int grid   = gridDim.x;
    const int ntiles = N / TILE;

    if (warp < 8) {
        // ======== PRODUCERS: w0-3 stream k, w4-7 stream v (pipelined across tiles) ========
        const bool isK  = warp < 4;
        const int  pt   = isK ? tid : (tid - 128);       // 0..127
        const int  qcol = (pt & 15) * 4;
        const float4* src = reinterpret_cast<const float4*>(isK ? kmat : vmat);
        const int  boff = isK ? 0 : KBUF;                // k at 0, v at KBUF

        float acc4[4] = {0.f, 0.f, 0.f, 0.f};            // k: colsums ; v: sv partial in acc4[0]

        float4 c0[8], c1r[8];
        {   // prologue: first tile's loads
            const float4* t0 = src + (size_t)blockIdx.x * 2048;
#pragma unroll
            for (int j = 0; j < 8; j++) c0[j]  = __ldcs(&t0[pt + j * 128]);
#pragma unroll
            for (int j = 0; j < 8; j++) c1r[j] = __ldcs(&t0[pt + (j + 8) * 128]);
        }

        int stage = 0, phase = 1;
        for (int tile = blockIdx.x; tile < ntiles; tile += grid) {
            int nt = tile + grid; if (nt >= ntiles) nt = tile;     // clamp (harmless reload)
            const float4* tn = src + (size_t)nt * 2048;

            mbar_wait(sh_u32(&mbar[DEPTH + stage]), phase);
            __half* dst = sh + stage * STAGE + boff;

            // chunk0: consume c0, then refill for next tile
#pragma unroll
            for (int j = 0; j < 8; j++) {
                float4 x = c0[j];
                int r = (pt + j * 128) >> 4;
                if (isK) { acc4[0] += x.x; acc4[1] += x.y; acc4[2] += x.z; acc4[3] += x.w; }
                else     { acc4[0] += x.x * x.x + x.y * x.y + x.z * x.z + x.w * x.w; }
                __half2 h01 = __floats2half2_rn(x.x, x.y);
                __half2 h23 = __floats2half2_rn(x.z, x.w);
                *reinterpret_cast<uint2*>(&dst[r * PH + qcol]) =
                    make_uint2(*reinterpret_cast<uint32_t*>(&h01), *reinterpret_cast<uint32_t*>(&h23));
            }
#pragma unroll
            for (int j = 0; j < 8; j++) c0[j] = __ldcs(&tn[pt + j * 128]);

            // chunk1: consume c1r, refill
#pragma unroll
            for (int j = 0; j < 8; j++) {
                float4 x = c1r[j];
                int r = (pt + (j + 8) * 128) >> 4;
                if (isK) { acc4[0] += x.x; acc4[1] += x.y; acc4[2] += x.z; acc4[3] += x.w; }
                else     { acc4[0] += x.x * x.x + x.y * x.y + x.z * x.z + x.w * x.w; }
                __half2 h01 = __floats2half2_rn(x.x, x.y);
                __half2 h23 = __floats2half2_rn(x.z, x.w);
                *reinterpret_cast<uint2*>(&dst[r * PH + qcol]) =
                    make_uint2(*reinterpret_cast<uint32_t*>(&h01), *reinterpret_cast<uint32_t*>(&h23));
            }
#pragma unroll
            for (int j = 0; j < 8; j++) c1r[j] = __ldcs(&tn[pt + (j + 8) * 128]);

            mbar_arrive(sh_u32(&mbar[stage]));
            stage++; if (stage == DEPTH) { stage = 0; phase ^= 1; }
        }

        if (isK) {
#pragma unroll
            for (int c = 0; c < 4; c++) atomicAdd(&g_ksum[qcol + c], acc4[c]);
        } else {
            float sv = acc4[0];
#pragma unroll
            for (int off = 16; off > 0; off >>= 1) sv += __shfl_xor_sync(0xFFFFFFFF, sv, off);
            if (lane == 0) atomicAdd(&g_sv, sv);
        }

    } else if (warp < 12) {
        // ======== GEMM1 warps (4): each M=32 (two 16-row stripes) ========
        const int widx = warp - 8;
        const int lp = lane >> 2, lq = lane & 3;

        uint32_t wr[4][4][4];
#pragma unroll
        for (int kk = 0; kk < 4; kk++)
#pragma unroll
            for (int j = 0; j < 4; j++) {
                const int bt = (2 * j + (lane >> 4)) * 8 + (lane & 7);
                const int bc = kk * 16 + ((lane >> 3) & 1) * 8;
                ldsm4(wr[kk][j][0], wr[kk][j][1], wr[kk][j][2], wr[kk][j][3],
                      sh_u32(&wsh[bt * PH + bc]));
            }

        int stage = 0, phase = 0;
        for (int tile = blockIdx.x; tile < ntiles; tile += grid) {
            mbar_wait(sh_u32(&mbar[stage]), phase);
            const __half* kb = sh + stage * STAGE;

#pragma unroll
            for (int s2 = 0; s2 < 2; s2++) {
                const int rbase = widx * 32 + s2 * 16;
                uint32_t af[4][4];
#pragma unroll
                for (int kk = 0; kk < 4; kk++)
                    ldsm4(af[kk][0], af[kk][1], af[kk][2], af[kk][3],
                          sh_u32(&kb[(rbase + (lane & 15)) * PH + kk * 16 + ((lane >> 4) << 3)]));
                if (s2 == 1 && lane == 0) mbar_arrive(sh_u32(&mbar[DEPTH + stage]));

                float c1[8][4];
#pragma unroll
                for (int n = 0; n < 8; n++)
#pragma unroll
                    for (int i = 0; i < 4; i++) c1[n][i] = 0.0f;
#pragma unroll
                for (int kk = 0; kk < 4; kk++)
#pragma unroll
                    for (int j = 0; j < 4; j++) {
                        mma16(c1[2 * j],     af[kk][0], af[kk][1], af[kk][2], af[kk][3],
                              wr[kk][j][0], wr[kk][j][1]);
                        mma16(c1[2 * j + 1], af[kk][0], af[kk][1], af[kk][2], af[kk][3],
                              wr[kk][j][2], wr[kk][j][3]);
                    }

                const size_t gr0 = (size_t)(tile * TILE + rbase + lp) * D;
#pragma unroll
                for (int n = 0; n < 8; n++) {
                    const int col = n * 8 + 2 * lq;
                    *reinterpret_cast<float2*>(&ret[gr0 + col])         = make_float2(c1[n][0], c1[n][1]);
                    *reinterpret_cast<float2*>(&ret[gr0 + 8 * D + col]) = make_float2(c1[n][2], c1[n][3]);
                }
            }
            stage++; if (stage == DEPTH) { stage = 0; phase ^= 1; }
        }

    } else {
        // ======== Reduction warps (4): symmetric G1 + G2, fragment reuse ========
        const int ridx = warp - 12;
        const int lp = lane >> 2, lq = lane & 3;

        float acc[7][8];
#pragma unroll
        for (int b = 0; b < 7; b++)
#pragma unroll
            for (int i = 0; i < 8; i++) acc[b][i] = 0.0f;

        int stage = 0, phase = 0;
        for (int tile = blockIdx.x; tile < ntiles; tile += grid) {
            mbar_wait(sh_u32(&mbar[stage]), phase);
            const __half* kb = sh + stage * STAGE;
            const __half* vb = kb + KBUF;

            if      (ridx == 0) red_tile_w0(acc, kb, vb, lane);
            else if (ridx == 1) red_tile_w1(acc, kb, vb, lane);
            else if (ridx == 2) red_tile_w2(acc, kb, vb, lane);
            else                red_tile_w3(acc, kb, vb, lane);

            if (lane == 0) mbar_arrive(sh_u32(&mbar[DEPTH + stage]));
            stage++; if (stage == DEPTH) { stage = 0; phase ^= 1; }
        }

        const int cnt = RW_CNT[ridx];
        for (int b = 0; b < cnt; b++) {
            const int enc = RW_TBL[ridx][b];
            const int src = (enc >> 4) & 1, ar = (enc >> 2) & 3, ac = enc & 3;
            float* gd = src ? g_G2 : g_G1;
            const int r0 = (ar * 16 + lp) * D + ac * 16;
            const int r1 = (ar * 16 + 8 + lp) * D + ac * 16;
            atomicAdd(&gd[r0 + 2 * lq],         acc[b][0]);
            atomicAdd(&gd[r0 + 2 * lq + 1],     acc[b][1]);
            atomicAdd(&gd[r1 + 2 * lq],         acc[b][2]);
            atomicAdd(&gd[r1 + 2 * lq + 1],     acc[b][3]);
            atomicAdd(&gd[r0 + 8 + 2 * lq],     acc[b][4]);
            atomicAdd(&gd[r0 + 8 + 2 * lq + 1], acc[b][5]);
            atomicAdd(&gd[r1 + 8 + 2 * lq],     acc[b][6]);
            atomicAdd(&gd[r1 + 8 + 2 * lq + 1], acc[b][7]);
        }
    }
}

__global__ void titans_final_kernel(const float* __restrict__ W,
                                    const float* __restrict__ gate_w,
                                    const float* __restrict__ gate_b,
                                    const float* __restrict__ S,
                                    float* __restrict__ out,
                                    int N) {
    __shared__ float Wsh[D * D];
    __shared__ float G1sh[D * D];
    __shared__ float gates_sh[3];
    __shared__ float red[256];
    __shared__ float red2[256];
    __shared__ float scale_sh;
    const int tid = threadIdx.x;
    const float numel = (float)N * (float)D;

    const size_t loss_off = (size_t)N * D;
    const size_t nw_off   = loss_off + 1;
    const size_t ns_off   = nw_off + D * D;
    const size_t g_off    = ns_off + D * D;

    for (int i = tid; i < D * D; i += 256) {
        Wsh[i] = W[i];
        const int j = i >> 6, d = i & 63;
        G1sh[i] = ((j >> 4) <= (d >> 4)) ? g_G1[i] : g_G1[(d << 6) | j];
    }
    if (tid == 0) {
        float invN = 1.0f / (float)N;
        for (int i = 0; i < 3; i++) {
            float sg = gate_b[i];
            for (int d = 0; d < D; d++) sg += gate_w[i * D + d] * (g_ksum[d] * invN);
            gates_sh[i] = 1.0f / (1.0f + __expf(-sg));
        }
    }
    __syncthreads();
    const float alpha = gates_sh[0];
    const float eta   = gates_sh[1];
    const float theta = gates_sh[2];

    float wg1[16];
    float dWW = 0.0f, dG2W = 0.0f;
#pragma unroll
    for (int i = 0; i < 16; i++) {
        int idx = tid * 16 + i;
        int j = idx >> 6, dp = idx & 63;
        float a = 0.0f;
#pragma unroll 8
        for (int d = 0; d < D; d++)
            a += Wsh[j * D + d] * G1sh[d * D + dp];
        wg1[i] = a;
        dWW  += a * Wsh[idx];
        dG2W += g_G2[idx] * Wsh[idx];
    }

    float wlocal[16];
    float ss = 0.0f;
#pragma unroll
    for (int i = 0; i < 16; i++) {
        int idx = tid * 16 + i;
        float g = (wg1[i] - g_G2[idx]) * (2.0f / numel);
        g = fminf(1.0f, fmaxf(-1.0f, g));
        float ns = eta * S[idx] - 0.01f * theta * g;
        float nw = (1.0f - alpha) * Wsh[idx] + ns;
        out[ns_off + idx] = ns;
        wlocal[i] = nw;
        ss += nw * nw;
    }

    red[tid]  = ss;
    red2[tid] = dWW - 2.0f * dG2W;
    __syncthreads();
#pragma unroll
    for (int s = 128; s > 0; s >>= 1) {
        if (tid < s) { red[tid] += red[tid + s]; red2[tid] += red2[tid + s]; }
        __syncthreads();
    }
    if (tid == 0) {
        float wnorm = sqrtf(red[0]);
        scale_sh = (wnorm > 10.0f) ? (10.0f / (wnorm + 1e-8f)) : 1.0f;
        out[loss_off] = (g_sv + red2[0]) / numel;
    }
    __syncthreads();
    const float sc = scale_sh;
#pragma unroll
    for (int i = 0; i < 16; i++) {
        int idx = tid * 16 + i;
        out[nw_off + idx] = wlocal[i] * sc;
    }
    if (tid < 3) out[g_off + tid] = gates_sh[tid];

    // re-zero scratch for the next graph replay
    __syncthreads();
    for (int i = tid; i < D * D; i += 256) { g_G1[i] = 0.0f; g_G2[i] = 0.0f; }
    if (tid < D) g_ksum[tid] = 0.0f;
    if (tid == 0) g_sv = 0.0f;
}

extern "C" void kernel_launch(void* const* d_in, const int* in_sizes, int n_in,
                              void* d_out, int out_size) {
    const float* k  = (const float*)d_in[0];
    const float* v  = (const float*)d_in[1];
    const float* W  = (const float*)d_in[2];
    const float* gw = (const float*)d_in[3];
    const float* gb = (const float*)d_in[4];
    const float* S  = (const float*)d_in[5];
    float* out = (float*)d_out;

    const int N = in_sizes[0] / D;

    cudaFuncSetAttribute(titans_main_kernel,
                         cudaFuncAttributeMaxDynamicSharedMemorySize, SMEM_BYTES);

    titans_main_kernel<<<148, 512, SMEM_BYTES>>>(k, v, W, out, N);
    titans_final_kernel<<<1, 256>>>(W, gw, gb, S, out, N);
}

// round 9
// speedup vs baseline: 1.0507x; 1.0094x over previous
#include <cuda_runtime.h>
#include <cuda_fp16.h>
#include <cstdint>

// TitansMemoryModule — pipelined producers (8 warps) + fragment-reuse reductions.
//   retrieved = k @ W^T ; G1 = k^T k (upper blocks, symmetric) ; G2 = v^T k
//   grad = (2/numel)(W G1 - G2) ; loss = (<W G1,W> - 2<G2,W> + sum v^2)/numel
// 512 thr: w0-3 k-producers, w4-7 v-producers, w8-11 GEMM1 (M=32 each), w12-15 reductions.
// R9: final kernel gate computation parallelized (was 41.7us serial-scalar tail).

#define D     64
#define TILE  128
#define PH    72
#define DEPTH 4

static constexpr int KBUF  = TILE * PH;
static constexpr int STAGE = 2 * KBUF;
static constexpr int SMEM_HALVES = DEPTH * STAGE + D * PH;
static constexpr int SMEM_BYTES  = SMEM_HALVES * 2;   // 156672 B

__device__ float g_G1[D * D];     // zero-init at load; re-zeroed by final kernel
__device__ float g_G2[D * D];
__device__ float g_ksum[D];
__device__ float g_sv;

__device__ __forceinline__ uint32_t sh_u32(const void* p) {
    return (uint32_t)__cvta_generic_to_shared(p);
}
__device__ __forceinline__ void ldsm4(uint32_t& r0, uint32_t& r1, uint32_t& r2, uint32_t& r3, uint32_t a) {
    asm volatile("ldmatrix.sync.aligned.m8n8.x4.shared.b16 {%0,%1,%2,%3},[%4];"
                 : "=r"(r0), "=r"(r1), "=r"(r2), "=r"(r3) : "r"(a));
}
__device__ __forceinline__ void ldsm4t(uint32_t& r0, uint32_t& r1, uint32_t& r2, uint32_t& r3, uint32_t a) {
    asm volatile("ldmatrix.sync.aligned.m8n8.x4.trans.shared.b16 {%0,%1,%2,%3},[%4];"
                 : "=r"(r0), "=r"(r1), "=r"(r2), "=r"(r3) : "r"(a));
}
__device__ __forceinline__ void mma16(float* c,
                                      uint32_t a0, uint32_t a1, uint32_t a2, uint32_t a3,
                                      uint32_t b0, uint32_t b1) {
    asm volatile("mma.sync.aligned.m16n8k16.row.col.f32.f16.f16.f32 "
                 "{%0,%1,%2,%3},{%4,%5,%6,%7},{%8,%9},{%0,%1,%2,%3};"
                 : "+f"(c[0]), "+f"(c[1]), "+f"(c[2]), "+f"(c[3])
                 : "r"(a0), "r"(a1), "r"(a2), "r"(a3), "r"(b0), "r"(b1));
}
__device__ __forceinline__ void mbar_init(uint32_t a, uint32_t cnt) {
    asm volatile("mbarrier.init.shared.b64 [%0], %1;" :: "r"(a), "r"(cnt) : "memory");
}
__device__ __forceinline__ void mbar_arrive(uint32_t a) {
    asm volatile("mbarrier.arrive.shared.b64 _, [%0];" :: "r"(a) : "memory");
}
__device__ __forceinline__ void mbar_wait(uint32_t a, uint32_t parity) {
    asm volatile(
        "{\n\t.reg .pred P;\n"
        "WL_%=:\n\t"
        "mbarrier.try_wait.parity.acquire.cta.shared::cta.b64 P, [%0], %1, 0x989680;\n\t"
        "@P bra WD_%=;\n\t"
        "bra WL_%=;\n"
        "WD_%=:\n\t}"
        :: "r"(a), "r"(parity) : "memory");
}

// ---- reduction helpers ----
__device__ __forceinline__ void ldAfrag(uint32_t* f, const __half* mb, int sb, int ar, int lane) {
    const int asel = ((lane >> 4) << 3) + (lane & 7);
    const int aoff = ((lane >> 3) & 1) * 8;
    ldsm4t(f[0], f[1], f[2], f[3], sh_u32(&mb[(sb + asel) * PH + ar * 16 + aoff]));
}
__device__ __forceinline__ void ldBfrag(uint32_t* f, const __half* kb, int sb, int ac, int lane) {
    const int bsel = ((lane >> 3) & 1) * 8 + (lane & 7);
    const int boff = (lane >> 4) * 8;
    ldsm4t(f[0], f[1], f[2], f[3], sh_u32(&kb[(sb + bsel) * PH + ac * 16 + boff]));
}
__device__ __forceinline__ void bmma(float* acc, const uint32_t* A, const uint32_t* B) {
    mma16(acc,     A[0], A[1], A[2], A[3], B[0], B[1]);
    mma16(acc + 4, A[0], A[1], A[2], A[3], B[2], B[3]);
}

// writeout tables: enc = src<<4 | ar<<2 | ac
static __device__ const int RW_TBL[4][7] = {
    { 0,  1,  2,  3,  5,  6,  7},          // w12: G1 (0,0..3),(1,1..3)
    {10, 11, 15, 16, 17, 18, 19},          // w13: G1 (2,2),(2,3),(3,3) + G2 (0,0..3)
    {20, 21, 22, 23, 24, 25, 25},          // w14: G2 (1,0..3),(2,0),(2,1)   [6 used]
    {26, 27, 28, 29, 30, 31, 31},          // w15: G2 (2,2),(2,3),(3,0..3)   [6 used]
};
static __device__ const int RW_CNT[4] = {7, 7, 6, 6};

__device__ __forceinline__ void red_tile_w0(float (&acc)[7][8], const __half* kb, const __half*, int lane) {
#pragma unroll
    for (int kk = 0; kk < 8; kk++) {
        const int sb = kk * 16;
        uint32_t A0[4], A1[4], B[4][4];
        ldAfrag(A0, kb, sb, 0, lane); ldAfrag(A1, kb, sb, 1, lane);
#pragma unroll
        for (int ac = 0; ac < 4; ac++) ldBfrag(B[ac], kb, sb, ac, lane);
        bmma(acc[0], A0, B[0]); bmma(acc[1], A0, B[1]);
        bmma(acc[2], A0, B[2]); bmma(acc[3], A0, B[3]);
        bmma(acc[4], A1, B[1]); bmma(acc[5], A1, B[2]); bmma(acc[6], A1, B[3]);
    }
}
__device__ __forceinline__ void red_tile_w1(float (&acc)[7][8], const __half* kb, const __half* vb, int lane) {
#pragma unroll
    for (int kk = 0; kk < 8; kk++) {
        const int sb = kk * 16;
        uint32_t A2[4], A3[4], AV[4], B[4][4];
        ldAfrag(A2, kb, sb, 2, lane); ldAfrag(A3, kb, sb, 3, lane); ldAfrag(AV, vb, sb, 0, lane);
#pragma unroll
        for (int ac = 0; ac < 4; ac++) ldBfrag(B[ac], kb, sb, ac, lane);
        bmma(acc[0], A2, B[2]); bmma(acc[1], A2, B[3]); bmma(acc[2], A3, B[3]);
        bmma(acc[3], AV, B[0]); bmma(acc[4], AV, B[1]);
        bmma(acc[5], AV, B[2]); bmma(acc[6], AV, B[3]);
    }
}
__device__ __forceinline__ void red_tile_w2(float (&acc)[7][8], const __half* kb, const __half* vb, int lane) {
#pragma unroll
    for (int kk = 0; kk < 8; kk++) {
        const int sb = kk * 16;
        uint32_t A1[4], A2[4], B[4][4];
        ldAfrag(A1, vb, sb, 1, lane); ldAfrag(A2, vb, sb, 2, lane);
#pragma unroll
        for (int ac = 0; ac < 4; ac++) ldBfrag(B[ac], kb, sb, ac, lane);
        bmma(acc[0], A1, B[0]); bmma(acc[1], A1, B[1]);
        bmma(acc[2], A1, B[2]); bmma(acc[3], A1, B[3]);
        bmma(acc[4], A2, B[0]); bmma(acc[5], A2, B[1]);
    }
}
__device__ __forceinline__ void red_tile_w3(float (&acc)[7][8], const __half* kb, const __half* vb, int lane) {
#pragma unroll
    for (int kk = 0; kk < 8; kk++) {
        const int sb = kk * 16;
        uint32_t A2[4], A3[4], B[4][4];
        ldAfrag(A2, vb, sb, 2, lane); ldAfrag(A3, vb, sb, 3, lane);
#pragma unroll
        for (int ac = 0; ac < 4; ac++) ldBfrag(B[ac], kb, sb, ac, lane);
        bmma(acc[0], A2, B[2]); bmma(acc[1], A2, B[3]);
        bmma(acc[2], A3, B[0]); bmma(acc[3], A3, B[1]);
        bmma(acc[4], A3, B[2]); bmma(acc[5], A3, B[3]);
    }
}

__global__ __launch_bounds__(512, 1)
void titans_main_kernel(const float* __restrict__ kmat,
                        const float* __restrict__ vmat,
                        const float* __restrict__ W,
                        float* __restrict__ ret,
                        int N) {
    extern __shared__ __half sh[];
    __shared__ uint64_t mbar[2 * DEPTH];   // [0..3] full, [4..7] empty
    __half* wsh = sh + DEPTH * STAGE;

    const int tid  = threadIdx.x;
    const int lane = tid & 31;
    const int warp = tid >> 5;

    if (tid == 0) {
#pragma unroll
        for (int s = 0; s < DEPTH; s++) {
            mbar_init(sh_u32(&mbar[s]), 256);          // full: 256 producer threads
            mbar_init(sh_u32(&mbar[DEPTH + s]), 8);    // empty: 8 consumer warps
        }
    }
    for (int i = tid; i < D * D; i += 512)
        wsh[(i >> 6) * PH + (i & 63)] = __float2half(W[i]);
    __syncthreads();

    const int grid   = gridDim.x;
    const int ntiles = N / TILE;

    if (warp < 8) {
        // ======== PRODUCERS: w0-3 stream k, w4-7 stream v (pipelined across tiles) ========
        const bool isK  = warp < 4;
        const int  pt   = isK ? tid : (tid - 128);       // 0..127
        const int  qcol = (pt & 15) * 4;
        const float4* src = reinterpret_cast<const float4*>(isK ? kmat : vmat);
        const int  boff = isK ? 0 : KBUF;

        float acc4[4] = {0.f, 0.f, 0.f, 0.f};

        float4 c0[8], c1r[8];
        {
            const float4* t0 = src + (size_t)blockIdx.x * 2048;
#pragma unroll
            for (int j = 0; j < 8; j++) c0[j]  = __ldcs(&t0[pt + j * 128]);
#pragma unroll
            for (int j = 0; j < 8; j++) c1r[j] = __ldcs(&t0[pt + (j + 8) * 128]);
        }

        int stage = 0, phase = 1;
        for (int tile = blockIdx.x; tile < ntiles; tile += grid) {
            int nt = tile + grid; if (nt >= ntiles) nt = tile;
            const float4* tn = src + (size_t)nt * 2048;

            mbar_wait(sh_u32(&mbar[DEPTH + stage]), phase);
            __half* dst = sh + stage * STAGE + boff;

#pragma unroll
            for (int j = 0; j < 8; j++) {
                float4 x = c0[j];
                int r = (pt + j * 128) >> 4;
                if (isK) { acc4[0] += x.x; acc4[1] += x.y; acc4[2] += x.z; acc4[3] += x.w; }
                else     { acc4[0] += x.x * x.x + x.y * x.y + x.z * x.z + x.w * x.w; }
                __half2 h01 = __floats2half2_rn(x.x, x.y);
                __half2 h23 = __floats2half2_rn(x.z, x.w);
                *reinterpret_cast<uint2*>(&dst[r * PH + qcol]) =
                    make_uint2(*reinterpret_cast<uint32_t*>(&h01), *reinterpret_cast<uint32_t*>(&h23));
            }
#pragma unroll
            for (int j = 0; j < 8; j++) c0[j] = __ldcs(&tn[pt + j * 128]);

#pragma unroll
            for (int j = 0; j < 8; j++) {
                float4 x = c1r[j];
                int r = (pt + (j + 8) * 128) >> 4;
                if (isK) { acc4[0] += x.x; acc4[1] += x.y; acc4[2] += x.z; acc4[3] += x.w; }
                else     { acc4[0] += x.x * x.x + x.y * x.y + x.z * x.z + x.w * x.w; }
                __half2 h01 = __floats2half2_rn(x.x, x.y);
                __half2 h23 = __floats2half2_rn(x.z, x.w);
                *reinterpret_cast<uint2*>(&dst[r * PH + qcol]) =
                    make_uint2(*reinterpret_cast<uint32_t*>(&h01), *reinterpret_cast<uint32_t*>(&h23));
            }
#pragma unroll
            for (int j = 0; j < 8; j++) c1r[j] = __ldcs(&tn[pt + (j + 8) * 128]);

            mbar_arrive(sh_u32(&mbar[stage]));
            stage++; if (stage == DEPTH) { stage = 0; phase ^= 1; }
        }

        if (isK) {
#pragma unroll
            for (int c = 0; c < 4; c++) atomicAdd(&g_ksum[qcol + c], acc4[c]);
        } else {
            float sv = acc4[0];
#pragma unroll
            for (int off = 16; off > 0; off >>= 1) sv += __shfl_xor_sync(0xFFFFFFFF, sv, off);
            if (lane == 0) atomicAdd(&g_sv, sv);
        }

    } else if (warp < 12) {
        // ======== GEMM1 warps (4): each M=32 (two 16-row stripes) ========
        const int widx = warp - 8;
        const int lp = lane >> 2, lq = lane & 3;

        uint32_t wr[4][4][4];
#pragma unroll
        for (int kk = 0; kk < 4; kk++)
#pragma unroll
            for (int j = 0; j < 4; j++) {
                const int bt = (2 * j + (lane >> 4)) * 8 + (lane & 7);
                const int bc = kk * 16 + ((lane >> 3) & 1) * 8;
                ldsm4(wr[kk][j][0], wr[kk][j][1], wr[kk][j][2], wr[kk][j][3],
                      sh_u32(&wsh[bt * PH + bc]));
            }

        int stage = 0, phase = 0;
        for (int tile = blockIdx.x; tile < ntiles; tile += grid) {
            mbar_wait(sh_u32(&mbar[stage]), phase);
            const __half* kb = sh + stage * STAGE;

#pragma unroll
            for (int s2 = 0; s2 < 2; s2++) {
                const int rbase = widx * 32 + s2 * 16;
                uint32_t af[4][4];
#pragma unroll
                for (int kk = 0; kk < 4; kk++)
                    ldsm4(af[kk][0], af[kk][1], af[kk][2], af[kk][3],
                          sh_u32(&kb[(rbase + (lane & 15)) * PH + kk * 16 + ((lane >> 4) << 3)]));
                if (s2 == 1 && lane == 0) mbar_arrive(sh_u32(&mbar[DEPTH + stage]));

                float c1[8][4];
#pragma unroll
                for (int n = 0; n < 8; n++)
#pragma unroll
                    for (int i = 0; i < 4; i++) c1[n][i] = 0.0f;
#pragma unroll
                for (int kk = 0; kk < 4; kk++)
#pragma unroll
                    for (int j = 0; j < 4; j++) {
                        mma16(c1[2 * j],     af[kk][0], af[kk][1], af[kk][2], af[kk][3],
                              wr[kk][j][0], wr[kk][j][1]);
                        mma16(c1[2 * j + 1], af[kk][0], af[kk][1], af[kk][2], af[kk][3],
                              wr[kk][j][2], wr[kk][j][3]);
                    }

                const size_t gr0 = (size_t)(tile * TILE + rbase + lp) * D;
#pragma unroll
                for (int n = 0; n < 8; n++) {
                    const int col = n * 8 + 2 * lq;
                    *reinterpret_cast<float2*>(&ret[gr0 + col])         = make_float2(c1[n][0], c1[n][1]);
                    *reinterpret_cast<float2*>(&ret[gr0 + 8 * D + col]) = make_float2(c1[n][2], c1[n][3]);
                }
            }
            stage++; if (stage == DEPTH) { stage = 0; phase ^= 1; }
        }

    } else {
        // ======== Reduction warps (4): symmetric G1 + G2, fragment reuse ========
        const int ridx = warp - 12;
        const int lp = lane >> 2, lq = lane & 3;

        float acc[7][8];
#pragma unroll
        for (int b = 0; b < 7; b++)
#pragma unroll
            for (int i = 0; i < 8; i++) acc[b][i] = 0.0f;

        int stage = 0, phase = 0;
        for (int tile = blockIdx.x; tile < ntiles; tile += grid) {
            mbar_wait(sh_u32(&mbar[stage]), phase);
            const __half* kb = sh + stage * STAGE;
            const __half* vb = kb + KBUF;

            if      (ridx == 0) red_tile_w0(acc, kb, vb, lane);
            else if (ridx == 1) red_tile_w1(acc, kb, vb, lane);
            else if (ridx == 2) red_tile_w2(acc, kb, vb, lane);
            else                red_tile_w3(acc, kb, vb, lane);

            if (lane == 0) mbar_arrive(sh_u32(&mbar[DEPTH + stage]));
            stage++; if (stage == DEPTH) { stage = 0; phase ^= 1; }
        }

        const int cnt = RW_CNT[ridx];
        for (int b = 0; b < cnt; b++) {
            const int enc = RW_TBL[ridx][b];
            const int src = (enc >> 4) & 1, ar = (enc >> 2) & 3, ac = enc & 3;
            float* gd = src ? g_G2 : g_G1;
            const int r0 = (ar * 16 + lp) * D + ac * 16;
            const int r1 = (ar * 16 + 8 + lp) * D + ac * 16;
            atomicAdd(&gd[r0 + 2 * lq],         acc[b][0]);
            atomicAdd(&gd[r0 + 2 * lq + 1],     acc[b][1]);
            atomicAdd(&gd[r1 + 2 * lq],         acc[b][2]);
            atomicAdd(&gd[r1 + 2 * lq + 1],     acc[b][3]);
            atomicAdd(&gd[r0 + 8 + 2 * lq],     acc[b][4]);
            atomicAdd(&gd[r0 + 8 + 2 * lq + 1], acc[b][5]);
            atomicAdd(&gd[r1 + 8 + 2 * lq],     acc[b][6]);
            atomicAdd(&gd[r1 + 8 + 2 * lq + 1], acc[b][7]);
        }
    }
}

__global__ void titans_final_kernel(const float* __restrict__ W,
                                    const float* __restrict__ gate_w,
                                    const float* __restrict__ gate_b,
                                    const float* __restrict__ S,
                                    float* __restrict__ out,
                                    int N) {
    __shared__ float Wsh[D * D];
    __shared__ float G1sh[D * D];
    __shared__ float G2sh[D * D];
    __shared__ float gates_sh[3];
    __shared__ float red[256];
    __shared__ float red2[256];
    __shared__ float scale_sh;
    const int tid  = threadIdx.x;
    const int lane = tid & 31;
    const int warp = tid >> 5;
    const float numel = (float)N * (float)D;

    const size_t loss_off = (size_t)N * D;
    const size_t nw_off   = loss_off + 1;
    const size_t ns_off   = nw_off + D * D;
    const size_t g_off    = ns_off + D * D;

    // stage W, mirrored-symmetric G1, and G2 into smem (parallel loads)
    for (int i = tid; i < D * D; i += 256) {
        Wsh[i]  = W[i];
        G2sh[i] = g_G2[i];
        const int j = i >> 6, d = i & 63;
        G1sh[i] = ((j >> 4) <= (d >> 4)) ? g_G1[i] : g_G1[(d << 6) | j];
    }
    // gates: warps 0-2 compute gate[warp] via parallel loads + shuffle reduce
    if (warp < 3) {
        const float invN = 1.0f / (float)N;
        float s = gate_w[warp * D + lane]      * (g_ksum[lane]      * invN)
                + gate_w[warp * D + 32 + lane] * (g_ksum[32 + lane] * invN);
#pragma unroll
        for (int off = 16; off > 0; off >>= 1)
            s += __shfl_xor_sync(0xFFFFFFFF, s, off);
        if (lane == 0)
            gates_sh[warp] = 1.0f / (1.0f + __expf(-(s + gate_b[warp])));
    }
    __syncthreads();
    const float alpha = gates_sh[0];
    const float eta   = gates_sh[1];
    const float theta = gates_sh[2];

    float wg1[16];
    float dWW = 0.0f, dG2W = 0.0f;
#pragma unroll
    for (int i = 0; i < 16; i++) {
        int idx = tid * 16 + i;
        int j = idx >> 6, dp = idx & 63;
        float a = 0.0f;
#pragma unroll 8
        for (int d = 0; d < D; d++)
            a += Wsh[j * D + d] * G1sh[d * D + dp];
        wg1[i] = a;
        dWW  += a * Wsh[idx];
        dG2W += G2sh[idx] * Wsh[idx];
    }

    float wlocal[16];
    float ss = 0.0f;
#pragma unroll
    for (int i = 0; i < 16; i++) {
        int idx = tid * 16 + i;
        float g = (wg1[i] - G2sh[idx]) * (2.0f / numel);
        g = fminf(1.0f, fmaxf(-1.0f, g));
        float ns = eta * S[idx] - 0.01f * theta * g;
        float nw = (1.0f - alpha) * Wsh[idx] + ns;
        out[ns_off + idx] = ns;
        wlocal[i] = nw;
        ss += nw * nw;
    }

    red[tid]  = ss;
    red2[tid] = dWW - 2.0f * dG2W;
    __syncthreads();
#pragma unroll
    for (int s = 128; s > 0; s >>= 1) {
        if (tid < s) { red[tid] += red[tid + s]; red2[tid] += red2[tid + s]; }
        __syncthreads();
    }
    if (tid == 0) {
        float wnorm = sqrtf(red[0]);
        scale_sh = (wnorm > 10.0f) ? (10.0f / (wnorm + 1e-8f)) : 1.0f;
        out[loss_off] = (g_sv + red2[0]) / numel;
    }
    __syncthreads();
    const float sc = scale_sh;
#pragma unroll
    for (int i = 0; i < 16; i++) {
        int idx = tid * 16 + i;
        out[nw_off + idx] = wlocal[i] * sc;
    }
    if (tid < 3) out[g_off + tid] = gates_sh[tid];

    // re-zero scratch for the next graph replay
    __syncthreads();
    for (int i = tid; i < D * D; i += 256) { g_G1[i] = 0.0f; g_G2[i] = 0.0f; }
    if (tid < D) g_ksum[tid] = 0.0f;
    if (tid == 0) g_sv = 0.0f;
}

extern "C" void kernel_launch(void* const* d_in, const int* in_sizes, int n_in,
                              void* d_out, int out_size) {
    const float* k  = (const float*)d_in[0];
    const float* v  = (const float*)d_in[1];
    const float* W  = (const float*)d_in[2];
    const float* gw = (const float*)d_in[3];
    const float* gb = (const float*)d_in[4];
    const float* S  = (const float*)d_in[5];
    float* out = (float*)d_out;

    const int N = in_sizes[0] / D;

    cudaFuncSetAttribute(titans_main_kernel,
                         cudaFuncAttributeMaxDynamicSharedMemorySize, SMEM_BYTES);

    titans_main_kernel<<<148, 512, SMEM_BYTES>>>(k, v, W, out, N);
    titans_final_kernel<<<1, 256>>>(W, gw, gb, S, out, N);
}

// round 10
// speedup vs baseline: 1.1799x; 1.1230x over previous
#include <cuda_runtime.h>
#include <cuda_fp16.h>
#include <cstdint>

// TitansMemoryModule — pipelined producers + fragment-reuse reductions (main, unchanged from R9)
// R10: epilogue split into parallel final1 (32 blocks) + tiny final2 (serial tail was 38us).

#define D     64
#define TILE  128
#define PH    72
#define DEPTH 4

static constexpr int KBUF  = TILE * PH;
static constexpr int STAGE = 2 * KBUF;
static constexpr int SMEM_HALVES = DEPTH * STAGE + D * PH;
static constexpr int SMEM_BYTES  = SMEM_HALVES * 2;   // 156672 B

__device__ float g_G1[D * D];     // zero-init at load; re-zeroed by final2
__device__ float g_G2[D * D];
__device__ float g_ksum[D];
__device__ float g_sv;
__device__ float g_ss;
__device__ float g_dl;

__device__ __forceinline__ uint32_t sh_u32(const void* p) {
    return (uint32_t)__cvta_generic_to_shared(p);
}
__device__ __forceinline__ void ldsm4(uint32_t& r0, uint32_t& r1, uint32_t& r2, uint32_t& r3, uint32_t a) {
    asm volatile("ldmatrix.sync.aligned.m8n8.x4.shared.b16 {%0,%1,%2,%3},[%4];"
                 : "=r"(r0), "=r"(r1), "=r"(r2), "=r"(r3) : "r"(a));
}
__device__ __forceinline__ void ldsm4t(uint32_t& r0, uint32_t& r1, uint32_t& r2, uint32_t& r3, uint32_t a) {
    asm volatile("ldmatrix.sync.aligned.m8n8.x4.trans.shared.b16 {%0,%1,%2,%3},[%4];"
                 : "=r"(r0), "=r"(r1), "=r"(r2), "=r"(r3) : "r"(a));
}
__device__ __forceinline__ void mma16(float* c,
                                      uint32_t a0, uint32_t a1, uint32_t a2, uint32_t a3,
                                      uint32_t b0, uint32_t b1) {
    asm volatile("mma.sync.aligned.m16n8k16.row.col.f32.f16.f16.f32 "
                 "{%0,%1,%2,%3},{%4,%5,%6,%7},{%8,%9},{%0,%1,%2,%3};"
                 : "+f"(c[0]), "+f"(c[1]), "+f"(c[2]), "+f"(c[3])
                 : "r"(a0), "r"(a1), "r"(a2), "r"(a3), "r"(b0), "r"(b1));
}
__device__ __forceinline__ void mbar_init(uint32_t a, uint32_t cnt) {
    asm volatile("mbarrier.init.shared.b64 [%0], %1;" :: "r"(a), "r"(cnt) : "memory");
}
__device__ __forceinline__ void mbar_arrive(uint32_t a) {
    asm volatile("mbarrier.arrive.shared.b64 _, [%0];" :: "r"(a) : "memory");
}
__device__ __forceinline__ void mbar_wait(uint32_t a, uint32_t parity) {
    asm volatile(
        "{\n\t.reg .pred P;\n"
        "WL_%=:\n\t"
        "mbarrier.try_wait.parity.acquire.cta.shared::cta.b64 P, [%0], %1, 0x989680;\n\t"
        "@P bra WD_%=;\n\t"
        "bra WL_%=;\n"
        "WD_%=:\n\t}"
        :: "r"(a), "r"(parity) : "memory");
}

// ---- reduction helpers ----
__device__ __forceinline__ void ldAfrag(uint32_t* f, const __half* mb, int sb, int ar, int lane) {
    const int asel = ((lane >> 4) << 3) + (lane & 7);
    const int aoff = ((lane >> 3) & 1) * 8;
    ldsm4t(f[0], f[1], f[2], f[3], sh_u32(&mb[(sb + asel) * PH + ar * 16 + aoff]));
}
__device__ __forceinline__ void ldBfrag(uint32_t* f, const __half* kb, int sb, int ac, int lane) {
    const int bsel = ((lane >> 3) & 1) * 8 + (lane & 7);
    const int boff = (lane >> 4) * 8;
    ldsm4t(f[0], f[1], f[2], f[3], sh_u32(&kb[(sb + bsel) * PH + ac * 16 + boff]));
}
__device__ __forceinline__ void bmma(float* acc, const uint32_t* A, const uint32_t* B) {
    mma16(acc,     A[0], A[1], A[2], A[3], B[0], B[1]);
    mma16(acc + 4, A[0], A[1], A[2], A[3], B[2], B[3]);
}

// writeout tables: enc = src<<4 | ar<<2 | ac
static __device__ const int RW_TBL[4][7] = {
    { 0,  1,  2,  3,  5,  6,  7},
    {10, 11, 15, 16, 17, 18, 19},
    {20, 21, 22, 23, 24, 25, 25},
    {26, 27, 28, 29, 30, 31, 31},
};
static __device__ const int RW_CNT[4] = {7, 7, 6, 6};

__device__ __forceinline__ void red_tile_w0(float (&acc)[7][8], const __half* kb, const __half*, int lane) {
#pragma unroll
    for (int kk = 0; kk < 8; kk++) {
        const int sb = kk * 16;
        uint32_t A0[4], A1[4], B[4][4];
        ldAfrag(A0, kb, sb, 0, lane); ldAfrag(A1, kb, sb, 1, lane);
#pragma unroll
        for (int ac = 0; ac < 4; ac++) ldBfrag(B[ac], kb, sb, ac, lane);
        bmma(acc[0], A0, B[0]); bmma(acc[1], A0, B[1]);
        bmma(acc[2], A0, B[2]); bmma(acc[3], A0, B[3]);
        bmma(acc[4], A1, B[1]); bmma(acc[5], A1, B[2]); bmma(acc[6], A1, B[3]);
    }
}
__device__ __forceinline__ void red_tile_w1(float (&acc)[7][8], const __half* kb, const __half* vb, int lane) {
#pragma unroll
    for (int kk = 0; kk < 8; kk++) {
        const int sb = kk * 16;
        uint32_t A2[4], A3[4], AV[4], B[4][4];
        ldAfrag(A2, kb, sb, 2, lane); ldAfrag(A3, kb, sb, 3, lane); ldAfrag(AV, vb, sb, 0, lane);
#pragma unroll
        for (int ac = 0; ac < 4; ac++) ldBfrag(B[ac], kb, sb, ac, lane);
        bmma(acc[0], A2, B[2]); bmma(acc[1], A2, B[3]); bmma(acc[2], A3, B[3]);
        bmma(acc[3], AV, B[0]); bmma(acc[4], AV, B[1]);
        bmma(acc[5], AV, B[2]); bmma(acc[6], AV, B[3]);
    }
}
__device__ __forceinline__ void red_tile_w2(float (&acc)[7][8], const __half* kb, const __half* vb, int lane) {
#pragma unroll
    for (int kk = 0; kk < 8; kk++) {
        const int sb = kk * 16;
        uint32_t A1[4], A2[4], B[4][4];
        ldAfrag(A1, vb, sb, 1, lane); ldAfrag(A2, vb, sb, 2, lane);
#pragma unroll
        for (int ac = 0; ac < 4; ac++) ldBfrag(B[ac], kb, sb, ac, lane);
        bmma(acc[0], A1, B[0]); bmma(acc[1], A1, B[1]);
        bmma(acc[2], A1, B[2]); bmma(acc[3], A1, B[3]);
        bmma(acc[4], A2, B[0]); bmma(acc[5], A2, B[1]);
    }
}
__device__ __forceinline__ void red_tile_w3(float (&acc)[7][8], const __half* kb, const __half* vb, int lane) {
#pragma unroll
    for (int kk = 0; kk < 8; kk++) {
        const int sb = kk * 16;
        uint32_t A2[4], A3[4], B[4][4];
        ldAfrag(A2, vb, sb, 2, lane); ldAfrag(A3, vb, sb, 3, lane);
#pragma unroll
        for (int ac = 0; ac < 4; ac++) ldBfrag(B[ac], kb, sb, ac, lane);
        bmma(acc[0], A2, B[2]); bmma(acc[1], A2, B[3]);
        bmma(acc[2], A3, B[0]); bmma(acc[3], A3, B[1]);
        bmma(acc[4], A3, B[2]); bmma(acc[5], A3, B[3]);
    }
}

__global__ __launch_bounds__(512, 1)
void titans_main_kernel(const float* __restrict__ kmat,
                        const float* __restrict__ vmat,
                        const float* __restrict__ W,
                        float* __restrict__ ret,
                        int N) {
    extern __shared__ __half sh[];
    __shared__ uint64_t mbar[2 * DEPTH];
    __half* wsh = sh + DEPTH * STAGE;

    const int tid  = threadIdx.x;
    const int lane = tid & 31;
    const int warp = tid >> 5;

    if (tid == 0) {
#pragma unroll
        for (int s = 0; s < DEPTH; s++) {
            mbar_init(sh_u32(&mbar[s]), 256);
            mbar_init(sh_u32(&mbar[DEPTH + s]), 8);
        }
    }
    for (int i = tid; i < D * D; i += 512)
        wsh[(i >> 6) * PH + (i & 63)] = __float2half(W[i]);
    __syncthreads();

    const int grid   = gridDim.x;
    const int ntiles = N / TILE;

    if (warp < 8) {
        const bool isK  = warp < 4;
        const int  pt   = isK ? tid : (tid - 128);
        const int  qcol = (pt & 15) * 4;
        const float4* src = reinterpret_cast<const float4*>(isK ? kmat : vmat);
        const int  boff = isK ? 0 : KBUF;

        float acc4[4] = {0.f, 0.f, 0.f, 0.f};

        float4 c0[8], c1r[8];
        {
            const float4* t0 = src + (size_t)blockIdx.x * 2048;
#pragma unroll
            for (int j = 0; j < 8; j++) c0[j]  = __ldcs(&t0[pt + j * 128]);
#pragma unroll
            for (int j = 0; j < 8; j++) c1r[j] = __ldcs(&t0[pt + (j + 8) * 128]);
        }

        int stage = 0, phase = 1;
        for (int tile = blockIdx.x; tile < ntiles; tile += grid) {
            int nt = tile + grid; if (nt >= ntiles) nt = tile;
            const float4* tn = src + (size_t)nt * 2048;

            mbar_wait(sh_u32(&mbar[DEPTH + stage]), phase);
            __half* dst = sh + stage * STAGE + boff;

#pragma unroll
            for (int j = 0; j < 8; j++) {
                float4 x = c0[j];
                int r = (pt + j * 128) >> 4;
                if (isK) { acc4[0] += x.x; acc4[1] += x.y; acc4[2] += x.z; acc4[3] += x.w; }
                else     { acc4[0] += x.x * x.x + x.y * x.y + x.z * x.z + x.w * x.w; }
                __half2 h01 = __floats2half2_rn(x.x, x.y);
                __half2 h23 = __floats2half2_rn(x.z, x.w);
                *reinterpret_cast<uint2*>(&dst[r * PH + qcol]) =
                    make_uint2(*reinterpret_cast<uint32_t*>(&h01), *reinterpret_cast<uint32_t*>(&h23));
            }
#pragma unroll
            for (int j = 0; j < 8; j++) c0[j] = __ldcs(&tn[pt + j * 128]);

#pragma unroll
            for (int j = 0; j < 8; j++) {
                float4 x = c1r[j];
                int r = (pt + (j + 8) * 128) >> 4;
                if (isK) { acc4[0] += x.x; acc4[1] += x.y; acc4[2] += x.z; acc4[3] += x.w; }
                else     { acc4[0] += x.x * x.x + x.y * x.y + x.z * x.z + x.w * x.w; }
                __half2 h01 = __floats2half2_rn(x.x, x.y);
                __half2 h23 = __floats2half2_rn(x.z, x.w);
                *reinterpret_cast<uint2*>(&dst[r * PH + qcol]) =
                    make_uint2(*reinterpret_cast<uint32_t*>(&h01), *reinterpret_cast<uint32_t*>(&h23));
            }
#pragma unroll
            for (int j = 0; j < 8; j++) c1r[j] = __ldcs(&tn[pt + (j + 8) * 128]);

            mbar_arrive(sh_u32(&mbar[stage]));
            stage++; if (stage == DEPTH) { stage = 0; phase ^= 1; }
        }

        if (isK) {
#pragma unroll
            for (int c = 0; c < 4; c++) atomicAdd(&g_ksum[qcol + c], acc4[c]);
        } else {
            float sv = acc4[0];
#pragma unroll
            for (int off = 16; off > 0; off >>= 1) sv += __shfl_xor_sync(0xFFFFFFFF, sv, off);
            if (lane == 0) atomicAdd(&g_sv, sv);
        }

    } else if (warp < 12) {
        const int widx = warp - 8;
        const int lp = lane >> 2, lq = lane & 3;

        uint32_t wr[4][4][4];
#pragma unroll
        for (int kk = 0; kk < 4; kk++)
#pragma unroll
            for (int j = 0; j < 4; j++) {
                const int bt = (2 * j + (lane >> 4)) * 8 + (lane & 7);
                const int bc = kk * 16 + ((lane >> 3) & 1) * 8;
                ldsm4(wr[kk][j][0], wr[kk][j][1], wr[kk][j][2], wr[kk][j][3],
                      sh_u32(&wsh[bt * PH + bc]));
            }

        int stage = 0, phase = 0;
        for (int tile = blockIdx.x; tile < ntiles; tile += grid) {
            mbar_wait(sh_u32(&mbar[stage]), phase);
            const __half* kb = sh + stage * STAGE;

#pragma unroll
            for (int s2 = 0; s2 < 2; s2++) {
                const int rbase = widx * 32 + s2 * 16;
                uint32_t af[4][4];
#pragma unroll
                for (int kk = 0; kk < 4; kk++)
                    ldsm4(af[kk][0], af[kk][1], af[kk][2], af[kk][3],
                          sh_u32(&kb[(rbase + (lane & 15)) * PH + kk * 16 + ((lane >> 4) << 3)]));
                if (s2 == 1 && lane == 0) mbar_arrive(sh_u32(&mbar[DEPTH + stage]));

                float c1[8][4];
#pragma unroll
                for (int n = 0; n < 8; n++)
#pragma unroll
                    for (int i = 0; i < 4; i++) c1[n][i] = 0.0f;
#pragma unroll
                for (int kk = 0; kk < 4; kk++)
#pragma unroll
                    for (int j = 0; j < 4; j++) {
                        mma16(c1[2 * j],     af[kk][0], af[kk][1], af[kk][2], af[kk][3],
                              wr[kk][j][0], wr[kk][j][1]);
                        mma16(c1[2 * j + 1], af[kk][0], af[kk][1], af[kk][2], af[kk][3],
                              wr[kk][j][2], wr[kk][j][3]);
                    }

                const size_t gr0 = (size_t)(tile * TILE + rbase + lp) * D;
#pragma unroll
                for (int n = 0; n < 8; n++) {
                    const int col = n * 8 + 2 * lq;
                    *reinterpret_cast<float2*>(&ret[gr0 + col])         = make_float2(c1[n][0], c1[n][1]);
                    *reinterpret_cast<float2*>(&ret[gr0 + 8 * D + col]) = make_float2(c1[n][2], c1[n][3]);
                }
            }
            stage++; if (stage == DEPTH) { stage = 0; phase ^= 1; }
        }

    } else {
        const int ridx = warp - 12;
        const int lp = lane >> 2, lq = lane & 3;

        float acc[7][8];
#pragma unroll
        for (int b = 0; b < 7; b++)
#pragma unroll
            for (int i = 0; i < 8; i++) acc[b][i] = 0.0f;

        int stage = 0, phase = 0;
        for (int tile = blockIdx.x; tile < ntiles; tile += grid) {
            mbar_wait(sh_u32(&mbar[stage]), phase);
            const __half* kb = sh + stage * STAGE;
            const __half* vb = kb + KBUF;

            if      (ridx == 0) red_tile_w0(acc, kb, vb, lane);
            else if (ridx == 1) red_tile_w1(acc, kb, vb, lane);
            else if (ridx == 2) red_tile_w2(acc, kb, vb, lane);
            else                red_tile_w3(acc, kb, vb, lane);

            if (lane == 0) mbar_arrive(sh_u32(&mbar[DEPTH + stage]));
            stage++; if (stage == DEPTH) { stage = 0; phase ^= 1; }
        }

        const int cnt = RW_CNT[ridx];
        for (int b = 0; b < cnt; b++) {
            const int enc = RW_TBL[ridx][b];
            const int src = (enc >> 4) & 1, ar = (enc >> 2) & 3, ac = enc & 3;
            float* gd = src ? g_G2 : g_G1;
            const int r0 = (ar * 16 + lp) * D + ac * 16;
            const int r1 = (ar * 16 + 8 + lp) * D + ac * 16;
            atomicAdd(&gd[r0 + 2 * lq],         acc[b][0]);
            atomicAdd(&gd[r0 + 2 * lq + 1],     acc[b][1]);
            atomicAdd(&gd[r1 + 2 * lq],         acc[b][2]);
            atomicAdd(&gd[r1 + 2 * lq + 1],     acc[b][3]);
            atomicAdd(&gd[r0 + 8 + 2 * lq],     acc[b][4]);
            atomicAdd(&gd[r0 + 8 + 2 * lq + 1], acc[b][5]);
            atomicAdd(&gd[r1 + 8 + 2 * lq],     acc[b][6]);
            atomicAdd(&gd[r1 + 8 + 2 * lq + 1], acc[b][7]);
        }
    }
}

// gates helper: warps 0-2 each compute one gate (identical across blocks)
__device__ __forceinline__ void compute_gates(float* gates_sh, const float* gate_w,
                                              const float* gate_b, int warp, int lane, int N) {
    if (warp < 3) {
        const float invN = 1.0f / (float)N;
        float s = gate_w[warp * D + lane]      * (g_ksum[lane]      * invN)
                + gate_w[warp * D + 32 + lane] * (g_ksum[32 + lane] * invN);
#pragma unroll
        for (int off = 16; off > 0; off >>= 1)
            s += __shfl_xor_sync(0xFFFFFFFF, s, off);
        if (lane == 0)
            gates_sh[warp] = 1.0f / (1.0f + __expf(-(s + gate_b[warp])));
    }
}

// final1: 32 blocks x 128 threads — per-entry grad/new_S/new_W(unscaled) + norm partials
__global__ void titans_final1(const float* __restrict__ W,
                              const float* __restrict__ gate_w,
                              const float* __restrict__ gate_b,
                              const float* __restrict__ S,
                              float* __restrict__ out,
                              int N) {
    __shared__ float G1m[D * D];
    __shared__ float W2[2 * D];
    __shared__ float gates_sh[3];
    __shared__ float red[128], red2[128];
    const int tid  = threadIdx.x;
    const int bid  = blockIdx.x;
    const int lane = tid & 31;
    const int warp = tid >> 5;
    const float numel = (float)N * (float)D;

    const size_t loss_off = (size_t)N * D;
    const size_t nw_off   = loss_off + 1;
    const size_t ns_off   = nw_off + D * D;

    compute_gates(gates_sh, gate_w, gate_b, warp, lane, N);

    for (int i = tid; i < D * D; i += 128) {
        const int j = i >> 6, d = i & 63;
        G1m[i] = ((j >> 4) <= (d >> 4)) ? g_G1[i] : g_G1[(d << 6) | j];
    }
    W2[tid] = W[bid * 128 + tid];
    __syncthreads();

    const float alpha = gates_sh[0];
    const float eta   = gates_sh[1];
    const float theta = gates_sh[2];

    const int idx = bid * 128 + tid;
    const int jr  = tid >> 6;        // 0/1: which of this block's 2 W rows
    const int dp  = idx & 63;

    float a = 0.0f;
#pragma unroll 8
    for (int d = 0; d < D; d++)
        a += W2[jr * D + d] * G1m[d * D + dp];

    const float w  = W2[jr * D + dp];   // == W[idx] (row jr, col dp)
    const float g2 = g_G2[idx];
    float g = (a - g2) * (2.0f / numel);
    g = fminf(1.0f, fmaxf(-1.0f, g));
    const float ns = eta * S[idx] - 0.01f * theta * g;
    const float nw = (1.0f - alpha) * w + ns;
    out[ns_off + idx] = ns;
    out[nw_off + idx] = nw;             // unscaled; final2 rescales

    red[tid]  = nw * nw;
    red2[tid] = (a - 2.0f * g2) * w;    // dWW - 2*dG2W partial
    __syncthreads();
#pragma unroll
    for (int s = 64; s > 0; s >>= 1) {
        if (tid < s) { red[tid] += red[tid + s]; red2[tid] += red2[tid + s]; }
        __syncthreads();
    }
    if (tid == 0) {
        atomicAdd(&g_ss, red[0]);
        atomicAdd(&g_dl, red2[0]);
    }
}

// final2: 1 block — scale new_W, loss, gates, re-zero scratch
__global__ void titans_final2(const float* __restrict__ gate_w,
                              const float* __restrict__ gate_b,
                              float* __restrict__ out,
                              int N) {
    __shared__ float gates_sh[3];
    __shared__ float sc_sh;
    const int tid  = threadIdx.x;
    const int lane = tid & 31;
    const int warp = tid >> 5;
    const float numel = (float)N * (float)D;

    const size_t loss_off = (size_t)N * D;
    const size_t nw_off   = loss_off + 1;
    const size_t g_off    = nw_off + 2 * D * D;

    compute_gates(gates_sh, gate_w, gate_b, warp, lane, N);
    if (tid == 0) {
        float wnorm = sqrtf(g_ss);
        sc_sh = (wnorm > 10.0f) ? (10.0f / (wnorm + 1e-8f)) : 1.0f;
        out[loss_off] = (g_sv + g_dl) / numel;
    }
    __syncthreads();
    const float sc = sc_sh;
    for (int i = tid; i < D * D; i += 256)
        out[nw_off + i] *= sc;
    if (tid < 3) out[g_off + tid] = gates_sh[tid];

    // re-zero scratch for next graph replay (all reads complete)
    __syncthreads();
    for (int i = tid; i < D * D; i += 256) { g_G1[i] = 0.0f; g_G2[i] = 0.0f; }
    if (tid < D) g_ksum[tid] = 0.0f;
    if (tid == 0) { g_sv = 0.0f; g_ss = 0.0f; g_dl = 0.0f; }
}

extern "C" void kernel_launch(void* const* d_in, const int* in_sizes, int n_in,
                              void* d_out, int out_size) {
    const float* k  = (const float*)d_in[0];
    const float* v  = (const float*)d_in[1];
    const float* W  = (const float*)d_in[2];
    const float* gw = (const float*)d_in[3];
    const float* gb = (const float*)d_in[4];
    const float* S  = (const float*)d_in[5];
    float* out = (float*)d_out;

    const int N = in_sizes[0] / D;

    cudaFuncSetAttribute(titans_main_kernel,
                         cudaFuncAttributeMaxDynamicSharedMemorySize, SMEM_BYTES);

    titans_main_kernel<<<148, 512, SMEM_BYTES>>>(k, v, W, out, N);
    titans_final1<<<32, 128>>>(W, gw, gb, S, out, N);
    titans_final2<<<1, 256>>>(gw, gb, out, N);
}